// round 13
// baseline (speedup 1.0000x reference)
#include <cuda_runtime.h>
#include <math.h>
#include <float.h>

#define HH 15
#define WW 20
#define AA 12
#define KK 3600
#define NWRD 113      // ceil(3600/32)
#define POST 2000
#define NTILE 6441    // 113*114/2 upper-triangle 32x32 tiles
#define NWARPS_MASK 1808  // 113 blocks * 16 warps

// ---------------- scratch (no allocations allowed) ----------------
__device__ float    g_relu1[512*300];
__device__ float    g_y2[336*300];
__device__ float    g_boxes[KK*4];
__device__ float4   g_sb4[KK];
__device__ float    g_ss[KK];
__device__ float    g_areas[KK];
__device__ unsigned g_mask[KK*NWRD];
__device__ float    g_ov[KK*5];
__device__ float    g_maxov[KK];
__device__ int      g_arg[KK];
__device__ int      g_labels[KK];
__device__ int      g_counts[2];

// ---------------- packed f32x2 helpers (Blackwell) ----------------
__device__ __forceinline__ unsigned long long pk2(float lo, float hi) {
    unsigned long long r;
    asm("mov.b64 %0, {%1, %2};" : "=l"(r) : "f"(lo), "f"(hi));
    return r;
}
__device__ __forceinline__ void unpk2(unsigned long long v, float& lo, float& hi) {
    asm("mov.b64 {%0, %1}, %2;" : "=f"(lo), "=f"(hi) : "l"(v));
}
__device__ __forceinline__ void fma2(unsigned long long& d,
                                     unsigned long long a, unsigned long long b) {
    asm("fma.rn.f32x2 %0, %1, %2, %0;" : "+l"(d) : "l"(a), "l"(b));
}

// ---------------- helpers ----------------
__device__ __forceinline__ void get_anchor(int k, float& x1, float& y1,
                                           float& x2, float& y2, bool& ins) {
    int a = k % AA;  int pos = k / AA;
    int h = pos / WW, w = pos % WW;
    int r = a >> 2, s = a & 3;
    int wsi = (r == 0) ? 23 : ((r == 1) ? 16 : 11);
    int hsi = (r == 0) ? 12 : ((r == 1) ? 16 : 22);
    int scl = 4 << s;
    float wwf = (float)(wsi * scl), hhf = (float)(hsi * scl);
    float sx = (float)(w * 16), sy = (float)(h * 16);
    x1 = sx + 7.5f - 0.5f * (wwf - 1.f);
    y1 = sy + 7.5f - 0.5f * (hhf - 1.f);
    x2 = sx + 7.5f + 0.5f * (wwf - 1.f);
    y2 = sy + 7.5f + 0.5f * (hhf - 1.f);
    ins = (x1 >= 0.f) && (y1 >= 0.f) && (x2 < 320.f) && (y2 < 240.f);
}

template <int NWARP>
__device__ __forceinline__ float blk_sum(float v, float* red, int tid) {
#pragma unroll
    for (int o = 16; o > 0; o >>= 1) v += __shfl_down_sync(0xffffffffu, v, o);
    if ((tid & 31) == 0) red[tid >> 5] = v;
    __syncthreads();
    float s;
    if (tid == 0) { s = 0.f; for (int i = 0; i < NWARP; i++) s += red[i]; red[31] = s; }
    __syncthreads();
    s = red[31];
    __syncthreads();
    return s;
}

__device__ __forceinline__ double blk_sumd(double v, double* red, int tid) {
#pragma unroll
    for (int o = 16; o > 0; o >>= 1) v += __shfl_down_sync(0xffffffffu, v, o);
    if ((tid & 31) == 0) red[tid >> 5] = v;
    __syncthreads();
    double s;
    if (tid == 0) { s = 0.0; for (int i = 0; i < 32; i++) s += red[i]; red[0] = s; }
    __syncthreads();
    s = red[0];
    __syncthreads();
    return s;
}

// ---------------- no-op (profile-slot alignment) ----------------
__global__ void k_nop() {}

// ---------------- conv1 3x3 (512->512) + BN(train) + ReLU ----------------
// grid 256, block 640 (20 warps). Block: 2 oc over 300 positions.
// 4-way ic-split: quarter q (5 warps, warp-uniform) does icl q*4..q*4+3.
// 4 fma2 accumulation chains per thread; division-free staging via u16 table.
__global__ void k_conv1(const float* __restrict__ x, const float* __restrict__ wgt,
                        const float* __restrict__ bias, const float* __restrict__ gg,
                        const float* __restrict__ bb) {
    __shared__ float xs[16 * 374];                // 16 ic x (17*22) padded
    __shared__ __align__(16) float ws[16 * 20];   // [icl][tap*2+ocl], pad 18->20
    __shared__ unsigned short sdst[4800];
    __shared__ float part[1800];                  // quarters 1-3 partials
    __shared__ float red[32];
    int tid = threadIdx.x;     // 640
    int oc0 = blockIdx.x * 2;
    int q = tid / 160;         // warp-uniform (160 = 5 warps)
    int lt = tid - q * 160;
    bool act = lt < 150;
    int h = lt / 10;
    int cw = (lt % 10) * 2;
    int icl0 = q * 4;
    unsigned long long q0a = 0, q0b = 0, q2a = 0, q2b = 0;

    for (int i = tid; i < 16 * 374; i += 640) xs[i] = 0.f;
    for (int i = tid; i < 4800; i += 640) {
        int icl = i / 300, p = i - icl * 300;
        sdst[i] = (unsigned short)(icl * 374 + (p / 20 + 1) * 22 + (p % 20 + 1));
    }
    __syncthreads();

    for (int cb = 0; cb < 32; cb++) {
        int icb = cb * 16;
        const float* xsrc = x + icb * 300;
#pragma unroll
        for (int i = tid; i < 4800; i += 640)
            xs[sdst[i]] = xsrc[i];
        if (tid < 288) {
            int icl = tid / 18, r = tid - icl * 18;
            int tap = r >> 1, ocl = r & 1;
            ws[icl * 20 + r] = wgt[(oc0 + ocl) * 4608 + (icb + icl) * 9 + tap];
        }
        __syncthreads();
        if (act) {
#pragma unroll
            for (int ii = 0; ii < 4; ii++) {
                int icl = icl0 + ii;
                const float* xp = &xs[icl * 374 + h * 22 + cw];
                float xv[3][4];
#pragma unroll
                for (int dh = 0; dh < 3; dh++) {
                    unsigned long long p01 =
                        *(const unsigned long long*)(xp + dh * 22);
                    unsigned long long p23 =
                        *(const unsigned long long*)(xp + dh * 22 + 2);
                    unpk2(p01, xv[dh][0], xv[dh][1]);
                    unpk2(p23, xv[dh][2], xv[dh][3]);
                }
                unsigned long long xd[3][4];
#pragma unroll
                for (int dh = 0; dh < 3; dh++)
#pragma unroll
                    for (int c = 0; c < 4; c++)
                        xd[dh][c] = pk2(xv[dh][c], xv[dh][c]);
                const float* wb = &ws[icl * 20];
                unsigned long long wt[9];
                {
                    ulonglong2 wA = *(const ulonglong2*)(wb);
                    ulonglong2 wB = *(const ulonglong2*)(wb + 4);
                    ulonglong2 wC = *(const ulonglong2*)(wb + 8);
                    ulonglong2 wD = *(const ulonglong2*)(wb + 12);
                    wt[0] = wA.x; wt[1] = wA.y; wt[2] = wB.x; wt[3] = wB.y;
                    wt[4] = wC.x; wt[5] = wC.y; wt[6] = wD.x; wt[7] = wD.y;
                    wt[8] = *(const unsigned long long*)(wb + 16);
                }
#pragma unroll
                for (int dh = 0; dh < 3; dh++)
#pragma unroll
                    for (int dw = 0; dw < 3; dw++) {
                        int tap = dh * 3 + dw;
                        unsigned long long w01 = wt[tap];
                        if (tap & 1) {
                            fma2(q0b, w01, xd[dh][dw]);
                            fma2(q2b, w01, xd[dh][dw + 1]);
                        } else {
                            fma2(q0a, w01, xd[dh][dw]);
                            fma2(q2a, w01, xd[dh][dw + 1]);
                        }
                    }
            }
        }
        __syncthreads();
    }

    // combine chains, then combine quarters
    float a00, a10, a01, a11;
    {
        float t0, t1, t2, t3;
        unpk2(q0a, t0, t1); unpk2(q0b, t2, t3);
        a00 = t0 + t2; a10 = t1 + t3;
        unpk2(q2a, t0, t1); unpk2(q2b, t2, t3);
        a01 = t0 + t2; a11 = t1 + t3;
    }
    if (act && q > 0) {
        int b = (q - 1) * 600 + lt * 4;
        part[b + 0] = a00; part[b + 1] = a10;
        part[b + 2] = a01; part[b + 3] = a11;
    }
    __syncthreads();
    bool actF = act && (q == 0);
    if (actF) {
#pragma unroll
        for (int g = 0; g < 3; g++) {
            int b = g * 600 + lt * 4;
            a00 += part[b + 0]; a10 += part[b + 1];
            a01 += part[b + 2]; a11 += part[b + 3];
        }
        a00 += bias[oc0 + 0]; a01 += bias[oc0 + 0];
        a10 += bias[oc0 + 1]; a11 += bias[oc0 + 1];
    }
    int p0 = actF ? (h * 20 + cw) : 0;
#define BN_OC(A0, A1, OCL)                                                            \
    {                                                                                 \
        float m = blk_sum<20>(actF ? (A0 + A1) : 0.f, red, tid) / 300.f;              \
        float d0 = A0 - m, d1 = A1 - m;                                               \
        float vv = blk_sum<20>(actF ? (d0 * d0 + d1 * d1) : 0.f, red, tid) / 300.f;   \
        if (actF) {                                                                   \
            float rs = rsqrtf(vv + 1e-5f) * gg[oc0 + OCL];                            \
            float o0 = d0 * rs + bb[oc0 + OCL];                                       \
            float o1 = d1 * rs + bb[oc0 + OCL];                                       \
            g_relu1[(oc0 + OCL) * 300 + p0] = fmaxf(o0, 0.f);                         \
            g_relu1[(oc0 + OCL) * 300 + p0 + 1] = fmaxf(o1, 0.f);                     \
        }                                                                             \
    }
    BN_OC(a00, a01, 0)
    BN_OC(a10, a11, 1)
#undef BN_OC
}

// ---------------- conv2 1x1 (512->336) + BN(train) ----------------
__global__ void k_conv2(const float* __restrict__ w2, const float* __restrict__ b2,
                        const float* __restrict__ g2, const float* __restrict__ bb2) {
    __shared__ __align__(16) float wst[2048];  // [ic][oc] for float4 loads
    __shared__ float red[32];
    int tid = threadIdx.x;
    int oc0 = blockIdx.x * 4;
    for (int i = tid; i < 2048; i += 320) {
        int ic = i >> 2, ocl = i & 3;
        wst[i] = w2[(oc0 + ocl) * 512 + ic];
    }
    __syncthreads();
    bool act = tid < 300;
    float a0 = 0, a1 = 0, a2 = 0, a3 = 0;
    if (act) {
#pragma unroll 4
        for (int ic = 0; ic < 512; ic++) {
            float rv = g_relu1[ic * 300 + tid];
            float4 wv = ((const float4*)wst)[ic];
            a0 += wv.x * rv; a1 += wv.y * rv; a2 += wv.z * rv; a3 += wv.w * rv;
        }
        a0 += b2[oc0 + 0]; a1 += b2[oc0 + 1]; a2 += b2[oc0 + 2]; a3 += b2[oc0 + 3];
    }
#define BN2_OC(A0, OCL)                                                         \
    {                                                                           \
        float m = blk_sum<10>(act ? A0 : 0.f, red, tid) / 300.f;                \
        float d = A0 - m;                                                       \
        float vv = blk_sum<10>(act ? d * d : 0.f, red, tid) / 300.f;            \
        if (act) {                                                              \
            g_y2[(oc0 + OCL) * 300 + tid] =                                     \
                d * rsqrtf(vv + 1e-5f) * g2[oc0 + OCL] + bb2[oc0 + OCL];        \
        }                                                                       \
    }
    BN2_OC(a0, 0)
    BN2_OC(a1, 1)
    BN2_OC(a2, 2)
    BN2_OC(a3, 3)
#undef BN2_OC
}

// ---------------- fused props + u64 bitonic sort ----------------
__device__ __forceinline__ void cex64(unsigned long long& a, unsigned long long& b,
                                      bool asc) {
    bool sw = asc ? (a > b) : (a < b);
    if (sw) { unsigned long long t = a; a = b; b = t; }
}

__global__ void k_sort() {
    __shared__ unsigned long long sk[4096];
    int tid = threadIdx.x;  // 1024

    for (int k = tid; k < 4096; k += 1024) {
        float sc = -FLT_MAX;
        if (k < KK) {
            int a = k % AA, pos = k / AA;
            float ax1, ay1, ax2, ay2; bool ins;
            get_anchor(k, ax1, ay1, ax2, ay2, ins);
            float wA = ax2 - ax1 + 1.f, hA = ay2 - ay1 + 1.f;
            float cx = ax1 + 0.5f * wA, cy = ay1 + 0.5f * hA;
            float d0 = g_y2[(24 + 4 * a + 0) * 300 + pos];
            float d1 = g_y2[(24 + 4 * a + 1) * 300 + pos];
            float d2 = g_y2[(24 + 4 * a + 2) * 300 + pos];
            float d3 = g_y2[(24 + 4 * a + 3) * 300 + pos];
            float pcx = d0 * wA + cx, pcy = d1 * hA + cy;
            float pw = expf(d2) * wA, ph = expf(d3) * hA;
            float x1 = pcx - 0.5f * pw, y1 = pcy - 0.5f * ph;
            float x2 = pcx + 0.5f * pw, y2 = pcy + 0.5f * ph;
            x1 = fminf(fmaxf(x1, 0.f), 319.f);
            y1 = fminf(fmaxf(y1, 0.f), 239.f);
            x2 = fminf(fmaxf(x2, 0.f), 319.f);
            y2 = fminf(fmaxf(y2, 0.f), 239.f);
            float wsz = x2 - x1 + 1.f, hsz = y2 - y1 + 1.f;
            float c0 = g_y2[a * 300 + pos], c1 = g_y2[(AA + a) * 300 + pos];
            float mm = fmaxf(c0, c1);
            float e0 = expf(c0 - mm), e1 = expf(c1 - mm);
            sc = e1 / (e0 + e1);
            if (!((wsz >= 8.f) && (hsz >= 8.f))) sc = -1e9f;
            g_boxes[k * 4 + 0] = x1;
            g_boxes[k * 4 + 1] = y1;
            g_boxes[k * 4 + 2] = x2;
            g_boxes[k * 4 + 3] = y2;
        }
        unsigned u = __float_as_uint(sc);
        unsigned ou = (u & 0x80000000u) ? ~u : (u | 0x80000000u);
        sk[k] = ((unsigned long long)(~ou) << 32) | (unsigned)k;
    }
    __syncthreads();

    {
        int b4 = tid * 4;
        unsigned long long k0 = sk[b4], k1 = sk[b4 + 1],
                           k2 = sk[b4 + 2], k3 = sk[b4 + 3];
        cex64(k0, k1, true);
        cex64(k2, k3, false);
        bool d4 = ((b4 & 4) == 0);
        cex64(k0, k2, d4); cex64(k1, k3, d4);
        cex64(k0, k1, d4); cex64(k2, k3, d4);
        sk[b4] = k0; sk[b4 + 1] = k1; sk[b4 + 2] = k2; sk[b4 + 3] = k3;
    }
    __syncthreads();

    for (int size = 8; size <= 4096; size <<= 1) {
        for (int stride = size >> 1; stride >= 4; stride >>= 1) {
            for (int i = tid; i < 4096; i += 1024) {
                int j = i ^ stride;
                if (j > i) {
                    bool asc = ((i & size) == 0);
                    unsigned long long ki = sk[i], kj = sk[j];
                    bool sw = asc ? (ki > kj) : (ki < kj);
                    if (sw) { sk[i] = kj; sk[j] = ki; }
                }
            }
            __syncthreads();
        }
        {
            int b4 = tid * 4;
            unsigned long long k0 = sk[b4], k1 = sk[b4 + 1],
                               k2 = sk[b4 + 2], k3 = sk[b4 + 3];
            bool dd = ((b4 & size) == 0);
            cex64(k0, k2, dd); cex64(k1, k3, dd);
            cex64(k0, k1, dd); cex64(k2, k3, dd);
            sk[b4] = k0; sk[b4 + 1] = k1; sk[b4 + 2] = k2; sk[b4 + 3] = k3;
        }
        __syncthreads();
    }

    for (int i = tid; i < KK; i += 1024) {
        unsigned long long kk = sk[i];
        int v = (int)(kk & 0xFFFFFFFFu);
        unsigned ou = ~((unsigned)(kk >> 32));
        unsigned u = (ou & 0x80000000u) ? (ou & 0x7FFFFFFFu) : ~ou;
        g_ss[i] = __uint_as_float(u);
        float x1 = g_boxes[v * 4 + 0], y1 = g_boxes[v * 4 + 1];
        float x2 = g_boxes[v * 4 + 2], y2 = g_boxes[v * 4 + 3];
        g_sb4[i] = make_float4(x1, y1, x2, y2);
        g_areas[i] = (x2 - x1 + 1.f) * (y2 - y1 + 1.f);
    }
}

// ---------------- NMS suppression bitmask (warp-per-32x32-tile) --------------
__global__ void k_mask(float* out, int out_size) {
    for (int i = blockIdx.x * 512 + threadIdx.x; i < out_size; i += 113 * 512)
        out[i] = 0.f;
    int lane = threadIdx.x & 31;
    int gw = blockIdx.x * 16 + (threadIdx.x >> 5);
    for (int tile = gw; tile < NTILE; tile += NWARPS_MASK) {
        int rw = (int)(113.5f - sqrtf(113.5f * 113.5f - 2.f * (float)tile));
        if (rw < 0) rw = 0;
        while ((rw + 1) * 113 - ((rw + 1) * rw) / 2 <= tile) rw++;
        while (rw * 113 - (rw * (rw - 1)) / 2 > tile) rw--;
        int cw = rw + (tile - (rw * 113 - (rw * (rw - 1)) / 2));
        int j = cw * 32 + lane;
        float4 bj = make_float4(0, 0, 0, 0);
        float aj = 1.f;
        bool jv = (j < KK);
        if (jv) {
            bj = g_sb4[j];
            aj = (bj.z - bj.x + 1.f) * (bj.w - bj.y + 1.f);
        }
        int rbase = rw * 32;
        unsigned myword = 0u;
#pragma unroll 4
        for (int r = 0; r < 32; r++) {
            int i = rbase + r;
            bool hit = false;
            if (i < KK) {
                float4 bi = g_sb4[i];   // broadcast load
                float ai = (bi.z - bi.x + 1.f) * (bi.w - bi.y + 1.f);
                if (jv && j > i) {
                    float xx1 = fmaxf(bi.x, bj.x), yy1 = fmaxf(bi.y, bj.y);
                    float xx2 = fminf(bi.z, bj.z), yy2 = fminf(bi.w, bj.w);
                    float iw = fmaxf(xx2 - xx1 + 1.f, 0.f);
                    float ih = fmaxf(yy2 - yy1 + 1.f, 0.f);
                    float inter = iw * ih;
                    float iou = inter / (ai + aj - inter);
                    hit = (iou > 0.7f);
                }
            }
            unsigned m = __ballot_sync(0xffffffffu, hit);
            if (lane == r) myword = m;
        }
        int i = rbase + lane;
        if (i < KK) g_mask[i * NWRD + cw] = myword;
    }
}

// ---------------- pipelined NMS scan + roi emit ----------------
__global__ void k_scan(float* out) {
    __shared__ unsigned s_remv[NWRD];
    __shared__ unsigned s_keep[NWRD];
    __shared__ unsigned s_diag[3][32];
    __shared__ unsigned s_next[3][32];
    __shared__ unsigned s_prio;
    __shared__ int pfx[NWRD + 1];
    int t = threadIdx.x;  // 128
    int lane = t & 31, wrp = t >> 5;
    if (t < NWRD) s_remv[t] = 0u;
    if (t == 0) s_prio = 0u;
    if (wrp == 1) {
        int i0 = lane;
        s_diag[0][lane] = g_mask[i0 * NWRD + 0];
        s_next[0][lane] = g_mask[i0 * NWRD + 1];
        int i1 = 32 + lane;
        s_diag[1][lane] = g_mask[i1 * NWRD + 1];
        s_next[1][lane] = g_mask[i1 * NWRD + 2];
    }
    __syncthreads();

    for (int s = 0; s < NWRD; s++) {
        int cur = s % 3;
        if (wrp == 1 && s + 2 < NWRD) {
            int i = (s + 2) * 32 + lane;
            unsigned dv = 0u, nv = 0u;
            if (i < KK) {
                dv = g_mask[i * NWRD + (s + 2)];
                if (s + 3 < NWRD) nv = g_mask[i * NWRD + (s + 3)];
            }
            s_diag[(s + 2) % 3][lane] = dv;
            s_next[(s + 2) % 3][lane] = nv;
        }
        if (wrp == 0) {
            unsigned nx = s_next[cur][lane];
            unsigned keep = 0u;
            if (lane == 0) {
                unsigned d[32];
#pragma unroll
                for (int b = 0; b < 32; b++) d[b] = s_diag[cur][b];
                unsigned actb = ~(s_remv[s] | s_prio);
                int lim = KK - s * 32; if (lim > 32) lim = 32;
#pragma unroll 8
                for (int b = 0; b < 32; b++) {
                    if (b < lim && ((actb >> b) & 1u)) {
                        keep |= (1u << b);
                        actb &= ~d[b];
                    }
                }
                s_keep[s] = keep;
            }
            keep = __shfl_sync(0xffffffffu, keep, 0);
            unsigned v = ((keep >> lane) & 1u) ? nx : 0u;
#pragma unroll
            for (int o = 16; o > 0; o >>= 1) v |= __shfl_xor_sync(0xffffffffu, v, o);
            if (lane == 0) s_prio = v;
        }
        if (wrp >= 2 && s >= 1) {
            unsigned kp = s_keep[s - 1];
            if (kp) {
                int rbase = (s - 1) * 32;
                for (int wd = s + 1 + (t - 64); wd < NWRD; wd += 64) {
                    unsigned acc = 0u;
                    unsigned k2 = kp;
                    while (k2) {
                        int b0 = __ffs(k2) - 1; k2 &= k2 - 1;
                        int b1 = -1, b2 = -1, b3 = -1;
                        if (k2) { b1 = __ffs(k2) - 1; k2 &= k2 - 1; }
                        if (k2) { b2 = __ffs(k2) - 1; k2 &= k2 - 1; }
                        if (k2) { b3 = __ffs(k2) - 1; k2 &= k2 - 1; }
                        unsigned m0 = g_mask[(rbase + b0) * NWRD + wd];
                        unsigned m1 = (b1 >= 0) ? g_mask[(rbase + b1) * NWRD + wd] : 0u;
                        unsigned m2 = (b2 >= 0) ? g_mask[(rbase + b2) * NWRD + wd] : 0u;
                        unsigned m3 = (b3 >= 0) ? g_mask[(rbase + b3) * NWRD + wd] : 0u;
                        acc |= (m0 | m1) | (m2 | m3);
                    }
                    s_remv[wd] |= acc;
                }
            }
        }
        __syncthreads();
    }

    if (t == 0) {
        int s = 0;
        for (int w = 0; w < NWRD; w++) { pfx[w] = s; s += __popc(s_keep[w]); }
        pfx[NWRD] = s;
    }
    __syncthreads();
    if (t < NWRD) {
        unsigned kp = s_keep[t];
        int r = pfx[t];
        while (kp) {
            int b = __ffs(kp) - 1;
            kp &= kp - 1;
            int i = t * 32 + b;
            if (r < POST && g_ss[i] > -1e8f) {
                float4 bb = g_sb4[i];
                out[3 + r * 5 + 1] = bb.x;
                out[3 + r * 5 + 2] = bb.y;
                out[3 + r * 5 + 3] = bb.z;
                out[3 + r * 5 + 4] = bb.w;
            }
            r++;
        }
    }
}

// ---------------- anchor target ----------------
__global__ void k_target(const float* __restrict__ gtb) {
    __shared__ float cm[32 * 5];
    __shared__ float colmax[5];
    __shared__ int cnt0, cnt1;
    int t = threadIdx.x;  // 1024
    if (t == 0) { cnt0 = 0; cnt1 = 0; }
    float gx1[5], gy1[5], gx2[5], gy2[5], ga[5];
#pragma unroll
    for (int g = 0; g < 5; g++) {
        gx1[g] = gtb[g * 5 + 0]; gy1[g] = gtb[g * 5 + 1];
        gx2[g] = gtb[g * 5 + 2]; gy2[g] = gtb[g * 5 + 3];
        ga[g] = (gx2[g] - gx1[g] + 1.f) * (gy2[g] - gy1[g] + 1.f);
    }
    float pc[5] = {-FLT_MAX, -FLT_MAX, -FLT_MAX, -FLT_MAX, -FLT_MAX};
    for (int k = t; k < KK; k += 1024) {
        float ax1, ay1, ax2, ay2; bool ins;
        get_anchor(k, ax1, ay1, ax2, ay2, ins);
        float aa = (ax2 - ax1 + 1.f) * (ay2 - ay1 + 1.f);
        float best = -FLT_MAX; int bg = 0;
#pragma unroll
        for (int g = 0; g < 5; g++) {
            float xx1 = fmaxf(ax1, gx1[g]), yy1 = fmaxf(ay1, gy1[g]);
            float xx2 = fminf(ax2, gx2[g]), yy2 = fminf(ay2, gy2[g]);
            float iw = fmaxf(xx2 - xx1 + 1.f, 0.f);
            float ih = fmaxf(yy2 - yy1 + 1.f, 0.f);
            float inter = iw * ih;
            float ov = inter / (aa + ga[g] - inter);
            ov = ins ? ov : -1.f;
            g_ov[k * 5 + g] = ov;
            pc[g] = fmaxf(pc[g], ov);
            if (ov > best) { best = ov; bg = g; }
        }
        g_maxov[k] = best;
        g_arg[k] = bg;
    }
#pragma unroll
    for (int g = 0; g < 5; g++) {
        float v = pc[g];
#pragma unroll
        for (int o = 16; o > 0; o >>= 1) v = fmaxf(v, __shfl_down_sync(0xffffffffu, v, o));
        if ((t & 31) == 0) cm[(t >> 5) * 5 + g] = v;
    }
    __syncthreads();
    if (t < 5) {
        float v = -FLT_MAX;
        for (int wpi = 0; wpi < 32; wpi++) v = fmaxf(v, cm[wpi * 5 + t]);
        colmax[t] = v;
    }
    __syncthreads();
    for (int k = t; k < KK; k += 1024) {
        float ax1, ay1, ax2, ay2; bool ins;
        get_anchor(k, ax1, ay1, ax2, ay2, ins);
        float mo = g_maxov[k];
        int lab = -1;
        if (ins && mo < 0.3f) lab = 0;
        bool gb = false;
#pragma unroll
        for (int g = 0; g < 5; g++)
            if (g_ov[k * 5 + g] == colmax[g]) gb = true;
        if (gb && ins) lab = 1;
        if (ins && mo >= 0.7f) lab = 1;
        g_labels[k] = lab;
        if (lab >= 0) atomicAdd(&cnt0, 1);
        if (lab == 1) atomicAdd(&cnt1, 1);
    }
    __syncthreads();
    if (t == 0) { g_counts[0] = cnt0; g_counts[1] = cnt1; }
}

// ---------------- losses ----------------
__global__ void k_loss(const float* __restrict__ gtb, float* out) {
    __shared__ double red[32];
    int t = threadIdx.x;  // 1024
    int nex = g_counts[0], nfg = g_counts[1];
    float num_ex = (float)(nex > 1 ? nex : 1);
    double scls = 0.0, sbox = 0.0, sact = 0.0;

    for (int i = t; i < KK; i += 1024) {
        int a = i / 300, pos = i - a * 300;
        int lab = g_labels[pos * 12 + a];
        if (lab != -1) {
            float x0 = g_y2[a * 300 + pos], x1 = g_y2[(12 + a) * 300 + pos];
            float m = fmaxf(x0, x1);
            float lse = m + logf(expf(x0 - m) + expf(x1 - m));
            float xl = lab ? x1 : x0;
            scls += (double)(lse - xl);
        }
    }

    for (int e = t; e < 14400; e += 1024) {
        int ch = e / 300, pos = e - ch * 300;
        int a = ch >> 2, c = ch & 3;
        int k = pos * 12 + a;
        int lab = g_labels[k];
        float ow = (lab >= 0) ? (1.f / num_ex) : 0.f;
        float iw = (lab == 1) ? 1.f : 0.f;
        float ax1, ay1, ax2, ay2; bool ins;
        get_anchor(k, ax1, ay1, ax2, ay2, ins);
        float tgt = 0.f;
        if (ins) {
            int g = g_arg[k];
            float gx1 = gtb[g * 5 + 0], gy1 = gtb[g * 5 + 1];
            float gx2 = gtb[g * 5 + 2], gy2 = gtb[g * 5 + 3];
            float ew = ax2 - ax1 + 1.f, eh = ay2 - ay1 + 1.f;
            float ecx = ax1 + 0.5f * ew, ecy = ay1 + 0.5f * eh;
            float gw = gx2 - gx1 + 1.f, gh = gy2 - gy1 + 1.f;
            float gcx = gx1 + 0.5f * gw, gcy = gy1 + 0.5f * gh;
            float tv;
            if (c == 0) tv = (gcx - ecx) / ew;
            else if (c == 1) tv = (gcy - ecy) / eh;
            else if (c == 2) tv = logf(gw / ew);
            else tv = logf(gh / eh);
            tgt = tv;
        }
        float pred = g_y2[(24 + ch) * 300 + pos];
        float d = iw * (pred - tgt);
        float ad = fabsf(d);
        float loss = (ad < (1.f / 9.f)) ? (0.5f * 9.f * d * d) : (ad - 0.5f / 9.f);
        sbox += (double)(ow * loss);
    }

    int gl = (int)gtb[4];
    for (int i = t; i < KK; i += 1024) {
        int a = i / 300, pos = i - a * 300;
        if (g_labels[pos * 12 + a] == 1) {
            float sa[22];
            float mx = -FLT_MAX;
#pragma unroll
            for (int n = 0; n < 22; n++) {
                int idx = i * 22 + n;
                int ch = idx / 300, pp = idx - ch * 300;
                float v = g_y2[(72 + ch) * 300 + pp];
                float s = 1.f / (1.f + expf(-v));
                sa[n] = s;
                mx = fmaxf(mx, s);
            }
            float se = 0.f;
#pragma unroll
            for (int n = 0; n < 22; n++) se += expf(sa[n] - mx);
            sact += (double)(mx + logf(se) - sa[gl]);
        }
    }

    double rs = blk_sumd(scls, red, t);
    double rb = blk_sumd(sbox, red, t);
    double ra = blk_sumd(sact, red, t);
    if (t == 0) {
        out[0] = (float)((rs / (double)nex) / 8.0);
        out[1] = (float)(rb / 8.0);
        out[2] = (float)(ra / (double)nfg);
    }
}

// ---------------- launch ----------------
extern "C" void kernel_launch(void* const* d_in, const int* in_sizes, int n_in,
                              void* d_out, int out_size) {
    const float* x   = (const float*)d_in[0];
    const float* gtb = (const float*)d_in[1];
    const float* w1  = (const float*)d_in[3];
    const float* b1  = (const float*)d_in[4];
    const float* g1  = (const float*)d_in[5];
    const float* bb1 = (const float*)d_in[6];
    const float* w2  = (const float*)d_in[7];
    const float* b2  = (const float*)d_in[8];
    const float* g2  = (const float*)d_in[9];
    const float* bb2 = (const float*)d_in[10];
    float* out = (float*)d_out;

    // launch #4 is the ncu-captured slot -> put conv2 there this round
    k_target<<<1, 1024>>>(gtb);                  // 1 (independent)
    k_nop<<<1, 32>>>();                          // 2
    k_conv1<<<256, 640>>>(x, w1, b1, g1, bb1);   // 3
    k_conv2<<<84, 320>>>(w2, b2, g2, bb2);       // 4 (profiled)
    k_sort<<<1, 1024>>>();                       // 5
    k_mask<<<113, 512>>>(out, out_size);         // 6
    k_scan<<<1, 128>>>(out);                     // 7
    k_loss<<<1, 1024>>>(gtb, out);               // 8
}

// round 14
// speedup vs baseline: 1.0033x; 1.0033x over previous
#include <cuda_runtime.h>
#include <math.h>
#include <float.h>

#define HH 15
#define WW 20
#define AA 12
#define KK 3600
#define NWRD 113      // ceil(3600/32)
#define POST 2000
#define NTILE 6441    // 113*114/2 upper-triangle 32x32 tiles
#define NWARPS_MASK 1808  // 113 blocks * 16 warps

// ---------------- scratch (no allocations allowed) ----------------
__device__ float    g_relu1[512*300];
__device__ float    g_y2[336*300];
__device__ float    g_boxes[KK*4];
__device__ float4   g_sb4[KK];
__device__ float    g_ss[KK];
__device__ float    g_areas[KK];
__device__ unsigned g_mask[KK*NWRD];
__device__ float    g_ov[KK*5];
__device__ float    g_maxov[KK];
__device__ int      g_arg[KK];
__device__ int      g_labels[KK];
__device__ int      g_counts[2];

// ---------------- packed f32x2 helpers (Blackwell) ----------------
__device__ __forceinline__ unsigned long long pk2(float lo, float hi) {
    unsigned long long r;
    asm("mov.b64 %0, {%1, %2};" : "=l"(r) : "f"(lo), "f"(hi));
    return r;
}
__device__ __forceinline__ void unpk2(unsigned long long v, float& lo, float& hi) {
    asm("mov.b64 {%0, %1}, %2;" : "=f"(lo), "=f"(hi) : "l"(v));
}
__device__ __forceinline__ void fma2(unsigned long long& d,
                                     unsigned long long a, unsigned long long b) {
    asm("fma.rn.f32x2 %0, %1, %2, %0;" : "+l"(d) : "l"(a), "l"(b));
}

// ---------------- helpers ----------------
__device__ __forceinline__ void get_anchor(int k, float& x1, float& y1,
                                           float& x2, float& y2, bool& ins) {
    int a = k % AA;  int pos = k / AA;
    int h = pos / WW, w = pos % WW;
    int r = a >> 2, s = a & 3;
    int wsi = (r == 0) ? 23 : ((r == 1) ? 16 : 11);
    int hsi = (r == 0) ? 12 : ((r == 1) ? 16 : 22);
    int scl = 4 << s;
    float wwf = (float)(wsi * scl), hhf = (float)(hsi * scl);
    float sx = (float)(w * 16), sy = (float)(h * 16);
    x1 = sx + 7.5f - 0.5f * (wwf - 1.f);
    y1 = sy + 7.5f - 0.5f * (hhf - 1.f);
    x2 = sx + 7.5f + 0.5f * (wwf - 1.f);
    y2 = sy + 7.5f + 0.5f * (hhf - 1.f);
    ins = (x1 >= 0.f) && (y1 >= 0.f) && (x2 < 320.f) && (y2 < 240.f);
}

template <int NWARP>
__device__ __forceinline__ float blk_sum(float v, float* red, int tid) {
#pragma unroll
    for (int o = 16; o > 0; o >>= 1) v += __shfl_down_sync(0xffffffffu, v, o);
    if ((tid & 31) == 0) red[tid >> 5] = v;
    __syncthreads();
    float s;
    if (tid == 0) { s = 0.f; for (int i = 0; i < NWARP; i++) s += red[i]; red[31] = s; }
    __syncthreads();
    s = red[31];
    __syncthreads();
    return s;
}

__device__ __forceinline__ double blk_sumd(double v, double* red, int tid) {
#pragma unroll
    for (int o = 16; o > 0; o >>= 1) v += __shfl_down_sync(0xffffffffu, v, o);
    if ((tid & 31) == 0) red[tid >> 5] = v;
    __syncthreads();
    double s;
    if (tid == 0) { s = 0.0; for (int i = 0; i < 32; i++) s += red[i]; red[0] = s; }
    __syncthreads();
    s = red[0];
    __syncthreads();
    return s;
}

// ---------------- conv1 3x3 (512->512) + BN(train) + ReLU ----------------
// grid 256, block 320 (10 warps). Block: 2 oc over 300 positions.
// ic-split: warps 0-4 do icl 0-7, warps 5-9 do icl 8-15 (combined via smem).
// 4 fma2 accumulation chains per thread; division-free staging via u16 table.
__global__ void k_conv1(const float* __restrict__ x, const float* __restrict__ wgt,
                        const float* __restrict__ bias, const float* __restrict__ gg,
                        const float* __restrict__ bb) {
    __shared__ float xs[16 * 374];                // 16 ic x (17*22) padded
    __shared__ __align__(16) float ws[16 * 20];   // [icl][tap*2+ocl], pad 18->20
    __shared__ unsigned short sdst[4800];
    __shared__ float part[150 * 4];
    __shared__ float red[32];
    int tid = threadIdx.x;     // 320
    int oc0 = blockIdx.x * 2;
    int half = tid / 160;      // warp-uniform (warp5 starts at 160)
    int lt = tid - half * 160;
    bool act = lt < 150;
    int h = lt / 10;
    int cw = (lt % 10) * 2;
    int icl0 = half * 8;
    unsigned long long q0a = 0, q0b = 0, q2a = 0, q2b = 0;

    for (int i = tid; i < 16 * 374; i += 320) xs[i] = 0.f;
    for (int i = tid; i < 4800; i += 320) {
        int icl = i / 300, p = i - icl * 300;
        sdst[i] = (unsigned short)(icl * 374 + (p / 20 + 1) * 22 + (p % 20 + 1));
    }
    __syncthreads();

    for (int cb = 0; cb < 32; cb++) {
        int icb = cb * 16;
        const float* xsrc = x + icb * 300;
#pragma unroll
        for (int i = tid; i < 4800; i += 320)
            xs[sdst[i]] = xsrc[i];
        if (tid < 288) {
            int icl = tid / 18, r = tid - icl * 18;
            int tap = r >> 1, ocl = r & 1;
            ws[icl * 20 + r] = wgt[(oc0 + ocl) * 4608 + (icb + icl) * 9 + tap];
        }
        __syncthreads();
        if (act) {
#pragma unroll
            for (int ii = 0; ii < 8; ii++) {
                int icl = icl0 + ii;
                const float* xp = &xs[icl * 374 + h * 22 + cw];
                float xv[3][4];
#pragma unroll
                for (int dh = 0; dh < 3; dh++) {
                    unsigned long long p01 =
                        *(const unsigned long long*)(xp + dh * 22);
                    unsigned long long p23 =
                        *(const unsigned long long*)(xp + dh * 22 + 2);
                    unpk2(p01, xv[dh][0], xv[dh][1]);
                    unpk2(p23, xv[dh][2], xv[dh][3]);
                }
                unsigned long long xd[3][4];
#pragma unroll
                for (int dh = 0; dh < 3; dh++)
#pragma unroll
                    for (int c = 0; c < 4; c++)
                        xd[dh][c] = pk2(xv[dh][c], xv[dh][c]);
                const float* wb = &ws[icl * 20];
                unsigned long long wt[9];
                {
                    ulonglong2 wA = *(const ulonglong2*)(wb);
                    ulonglong2 wB = *(const ulonglong2*)(wb + 4);
                    ulonglong2 wC = *(const ulonglong2*)(wb + 8);
                    ulonglong2 wD = *(const ulonglong2*)(wb + 12);
                    wt[0] = wA.x; wt[1] = wA.y; wt[2] = wB.x; wt[3] = wB.y;
                    wt[4] = wC.x; wt[5] = wC.y; wt[6] = wD.x; wt[7] = wD.y;
                    wt[8] = *(const unsigned long long*)(wb + 16);
                }
#pragma unroll
                for (int dh = 0; dh < 3; dh++)
#pragma unroll
                    for (int dw = 0; dw < 3; dw++) {
                        int tap = dh * 3 + dw;
                        unsigned long long w01 = wt[tap];
                        if (tap & 1) {
                            fma2(q0b, w01, xd[dh][dw]);
                            fma2(q2b, w01, xd[dh][dw + 1]);
                        } else {
                            fma2(q0a, w01, xd[dh][dw]);
                            fma2(q2a, w01, xd[dh][dw + 1]);
                        }
                    }
            }
        }
        __syncthreads();
    }

    // combine chains, then combine ic-halves
    float a00, a10, a01, a11;
    {
        float t0, t1, t2, t3;
        unpk2(q0a, t0, t1); unpk2(q0b, t2, t3);
        a00 = t0 + t2; a10 = t1 + t3;
        unpk2(q2a, t0, t1); unpk2(q2b, t2, t3);
        a01 = t0 + t2; a11 = t1 + t3;
    }
    if (act && half == 1) {
        part[lt * 4 + 0] = a00; part[lt * 4 + 1] = a10;
        part[lt * 4 + 2] = a01; part[lt * 4 + 3] = a11;
    }
    __syncthreads();
    bool actF = act && (half == 0);
    if (actF) {
        a00 += part[lt * 4 + 0]; a10 += part[lt * 4 + 1];
        a01 += part[lt * 4 + 2]; a11 += part[lt * 4 + 3];
        a00 += bias[oc0 + 0]; a01 += bias[oc0 + 0];
        a10 += bias[oc0 + 1]; a11 += bias[oc0 + 1];
    }
    int p0 = actF ? (h * 20 + cw) : 0;
#define BN_OC(A0, A1, OCL)                                                            \
    {                                                                                 \
        float m = blk_sum<10>(actF ? (A0 + A1) : 0.f, red, tid) / 300.f;              \
        float d0 = A0 - m, d1 = A1 - m;                                               \
        float vv = blk_sum<10>(actF ? (d0 * d0 + d1 * d1) : 0.f, red, tid) / 300.f;   \
        if (actF) {                                                                   \
            float rs = rsqrtf(vv + 1e-5f) * gg[oc0 + OCL];                            \
            float o0 = d0 * rs + bb[oc0 + OCL];                                       \
            float o1 = d1 * rs + bb[oc0 + OCL];                                       \
            g_relu1[(oc0 + OCL) * 300 + p0] = fmaxf(o0, 0.f);                         \
            g_relu1[(oc0 + OCL) * 300 + p0 + 1] = fmaxf(o1, 0.f);                     \
        }                                                                             \
    }
    BN_OC(a00, a01, 0)
    BN_OC(a10, a11, 1)
#undef BN_OC
}

// ---------------- conv2 1x1 (512->336) + BN(train) ----------------
// grid 84, block 640. 4 oc per block; 2-way ic split (halves of 256 ic) to
// halve the per-thread latency chain; partials combined via smem.
__global__ void k_conv2(const float* __restrict__ w2, const float* __restrict__ b2,
                        const float* __restrict__ g2, const float* __restrict__ bb2) {
    __shared__ __align__(16) float wst[2048];  // [ic][oc] for float4 loads
    __shared__ float part[300 * 4];
    __shared__ float red[32];
    int tid = threadIdx.x;     // 640
    int oc0 = blockIdx.x * 4;
    int half = tid / 320;      // warp-uniform
    int lt = tid - half * 320;
    for (int i = tid; i < 2048; i += 640) {
        int ic = i >> 2, ocl = i & 3;
        wst[i] = w2[(oc0 + ocl) * 512 + ic];
    }
    __syncthreads();
    bool act = lt < 300;
    float a0 = 0, a1 = 0, a2 = 0, a3 = 0;
    if (act) {
        int ic0 = half * 256;
#pragma unroll 8
        for (int ii = 0; ii < 256; ii++) {
            int ic = ic0 + ii;
            float rv = g_relu1[ic * 300 + lt];
            float4 wv = ((const float4*)wst)[ic];
            a0 += wv.x * rv; a1 += wv.y * rv; a2 += wv.z * rv; a3 += wv.w * rv;
        }
    }
    if (act && half == 1) {
        part[lt * 4 + 0] = a0; part[lt * 4 + 1] = a1;
        part[lt * 4 + 2] = a2; part[lt * 4 + 3] = a3;
    }
    __syncthreads();
    bool actF = act && (half == 0);
    if (actF) {
        a0 += part[lt * 4 + 0]; a1 += part[lt * 4 + 1];
        a2 += part[lt * 4 + 2]; a3 += part[lt * 4 + 3];
        a0 += b2[oc0 + 0]; a1 += b2[oc0 + 1]; a2 += b2[oc0 + 2]; a3 += b2[oc0 + 3];
    }
#define BN2_OC(A0, OCL)                                                         \
    {                                                                           \
        float m = blk_sum<20>(actF ? A0 : 0.f, red, tid) / 300.f;               \
        float d = A0 - m;                                                       \
        float vv = blk_sum<20>(actF ? d * d : 0.f, red, tid) / 300.f;           \
        if (actF) {                                                             \
            g_y2[(oc0 + OCL) * 300 + lt] =                                      \
                d * rsqrtf(vv + 1e-5f) * g2[oc0 + OCL] + bb2[oc0 + OCL];        \
        }                                                                       \
    }
    BN2_OC(a0, 0)
    BN2_OC(a1, 1)
    BN2_OC(a2, 2)
    BN2_OC(a3, 3)
#undef BN2_OC
}

// ---------------- fused props + u64 bitonic sort ----------------
__device__ __forceinline__ void cex64(unsigned long long& a, unsigned long long& b,
                                      bool asc) {
    bool sw = asc ? (a > b) : (a < b);
    if (sw) { unsigned long long t = a; a = b; b = t; }
}

__global__ void k_sort() {
    __shared__ unsigned long long sk[4096];
    int tid = threadIdx.x;  // 1024

    for (int k = tid; k < 4096; k += 1024) {
        float sc = -FLT_MAX;
        if (k < KK) {
            int a = k % AA, pos = k / AA;
            float ax1, ay1, ax2, ay2; bool ins;
            get_anchor(k, ax1, ay1, ax2, ay2, ins);
            float wA = ax2 - ax1 + 1.f, hA = ay2 - ay1 + 1.f;
            float cx = ax1 + 0.5f * wA, cy = ay1 + 0.5f * hA;
            float d0 = g_y2[(24 + 4 * a + 0) * 300 + pos];
            float d1 = g_y2[(24 + 4 * a + 1) * 300 + pos];
            float d2 = g_y2[(24 + 4 * a + 2) * 300 + pos];
            float d3 = g_y2[(24 + 4 * a + 3) * 300 + pos];
            float pcx = d0 * wA + cx, pcy = d1 * hA + cy;
            float pw = expf(d2) * wA, ph = expf(d3) * hA;
            float x1 = pcx - 0.5f * pw, y1 = pcy - 0.5f * ph;
            float x2 = pcx + 0.5f * pw, y2 = pcy + 0.5f * ph;
            x1 = fminf(fmaxf(x1, 0.f), 319.f);
            y1 = fminf(fmaxf(y1, 0.f), 239.f);
            x2 = fminf(fmaxf(x2, 0.f), 319.f);
            y2 = fminf(fmaxf(y2, 0.f), 239.f);
            float wsz = x2 - x1 + 1.f, hsz = y2 - y1 + 1.f;
            float c0 = g_y2[a * 300 + pos], c1 = g_y2[(AA + a) * 300 + pos];
            float mm = fmaxf(c0, c1);
            float e0 = expf(c0 - mm), e1 = expf(c1 - mm);
            sc = e1 / (e0 + e1);
            if (!((wsz >= 8.f) && (hsz >= 8.f))) sc = -1e9f;
            g_boxes[k * 4 + 0] = x1;
            g_boxes[k * 4 + 1] = y1;
            g_boxes[k * 4 + 2] = x2;
            g_boxes[k * 4 + 3] = y2;
        }
        unsigned u = __float_as_uint(sc);
        unsigned ou = (u & 0x80000000u) ? ~u : (u | 0x80000000u);
        sk[k] = ((unsigned long long)(~ou) << 32) | (unsigned)k;
    }
    __syncthreads();

    {
        int b4 = tid * 4;
        unsigned long long k0 = sk[b4], k1 = sk[b4 + 1],
                           k2 = sk[b4 + 2], k3 = sk[b4 + 3];
        cex64(k0, k1, true);
        cex64(k2, k3, false);
        bool d4 = ((b4 & 4) == 0);
        cex64(k0, k2, d4); cex64(k1, k3, d4);
        cex64(k0, k1, d4); cex64(k2, k3, d4);
        sk[b4] = k0; sk[b4 + 1] = k1; sk[b4 + 2] = k2; sk[b4 + 3] = k3;
    }
    __syncthreads();

    for (int size = 8; size <= 4096; size <<= 1) {
        for (int stride = size >> 1; stride >= 4; stride >>= 1) {
            for (int i = tid; i < 4096; i += 1024) {
                int j = i ^ stride;
                if (j > i) {
                    bool asc = ((i & size) == 0);
                    unsigned long long ki = sk[i], kj = sk[j];
                    bool sw = asc ? (ki > kj) : (ki < kj);
                    if (sw) { sk[i] = kj; sk[j] = ki; }
                }
            }
            __syncthreads();
        }
        {
            int b4 = tid * 4;
            unsigned long long k0 = sk[b4], k1 = sk[b4 + 1],
                               k2 = sk[b4 + 2], k3 = sk[b4 + 3];
            bool dd = ((b4 & size) == 0);
            cex64(k0, k2, dd); cex64(k1, k3, dd);
            cex64(k0, k1, dd); cex64(k2, k3, dd);
            sk[b4] = k0; sk[b4 + 1] = k1; sk[b4 + 2] = k2; sk[b4 + 3] = k3;
        }
        __syncthreads();
    }

    for (int i = tid; i < KK; i += 1024) {
        unsigned long long kk = sk[i];
        int v = (int)(kk & 0xFFFFFFFFu);
        unsigned ou = ~((unsigned)(kk >> 32));
        unsigned u = (ou & 0x80000000u) ? (ou & 0x7FFFFFFFu) : ~ou;
        g_ss[i] = __uint_as_float(u);
        float x1 = g_boxes[v * 4 + 0], y1 = g_boxes[v * 4 + 1];
        float x2 = g_boxes[v * 4 + 2], y2 = g_boxes[v * 4 + 3];
        g_sb4[i] = make_float4(x1, y1, x2, y2);
        g_areas[i] = (x2 - x1 + 1.f) * (y2 - y1 + 1.f);
    }
}

// ---------------- NMS suppression bitmask (warp-per-32x32-tile) --------------
__global__ void k_mask(float* out, int out_size) {
    for (int i = blockIdx.x * 512 + threadIdx.x; i < out_size; i += 113 * 512)
        out[i] = 0.f;
    int lane = threadIdx.x & 31;
    int gw = blockIdx.x * 16 + (threadIdx.x >> 5);
    for (int tile = gw; tile < NTILE; tile += NWARPS_MASK) {
        int rw = (int)(113.5f - sqrtf(113.5f * 113.5f - 2.f * (float)tile));
        if (rw < 0) rw = 0;
        while ((rw + 1) * 113 - ((rw + 1) * rw) / 2 <= tile) rw++;
        while (rw * 113 - (rw * (rw - 1)) / 2 > tile) rw--;
        int cw = rw + (tile - (rw * 113 - (rw * (rw - 1)) / 2));
        int j = cw * 32 + lane;
        float4 bj = make_float4(0, 0, 0, 0);
        float aj = 1.f;
        bool jv = (j < KK);
        if (jv) {
            bj = g_sb4[j];
            aj = (bj.z - bj.x + 1.f) * (bj.w - bj.y + 1.f);
        }
        int rbase = rw * 32;
        unsigned myword = 0u;
#pragma unroll 4
        for (int r = 0; r < 32; r++) {
            int i = rbase + r;
            bool hit = false;
            if (i < KK) {
                float4 bi = g_sb4[i];   // broadcast load
                float ai = (bi.z - bi.x + 1.f) * (bi.w - bi.y + 1.f);
                if (jv && j > i) {
                    float xx1 = fmaxf(bi.x, bj.x), yy1 = fmaxf(bi.y, bj.y);
                    float xx2 = fminf(bi.z, bj.z), yy2 = fminf(bi.w, bj.w);
                    float iw = fmaxf(xx2 - xx1 + 1.f, 0.f);
                    float ih = fmaxf(yy2 - yy1 + 1.f, 0.f);
                    float inter = iw * ih;
                    float iou = inter / (ai + aj - inter);
                    hit = (iou > 0.7f);
                }
            }
            unsigned m = __ballot_sync(0xffffffffu, hit);
            if (lane == r) myword = m;
        }
        int i = rbase + lane;
        if (i < KK) g_mask[i * NWRD + cw] = myword;
    }
}

// ---------------- pipelined NMS scan + roi emit ----------------
__global__ void k_scan(float* out) {
    __shared__ unsigned s_remv[NWRD];
    __shared__ unsigned s_keep[NWRD];
    __shared__ unsigned s_diag[3][32];
    __shared__ unsigned s_next[3][32];
    __shared__ unsigned s_prio;
    __shared__ int pfx[NWRD + 1];
    int t = threadIdx.x;  // 128
    int lane = t & 31, wrp = t >> 5;
    if (t < NWRD) s_remv[t] = 0u;
    if (t == 0) s_prio = 0u;
    if (wrp == 1) {
        int i0 = lane;
        s_diag[0][lane] = g_mask[i0 * NWRD + 0];
        s_next[0][lane] = g_mask[i0 * NWRD + 1];
        int i1 = 32 + lane;
        s_diag[1][lane] = g_mask[i1 * NWRD + 1];
        s_next[1][lane] = g_mask[i1 * NWRD + 2];
    }
    __syncthreads();

    for (int s = 0; s < NWRD; s++) {
        int cur = s % 3;
        if (wrp == 1 && s + 2 < NWRD) {
            int i = (s + 2) * 32 + lane;
            unsigned dv = 0u, nv = 0u;
            if (i < KK) {
                dv = g_mask[i * NWRD + (s + 2)];
                if (s + 3 < NWRD) nv = g_mask[i * NWRD + (s + 3)];
            }
            s_diag[(s + 2) % 3][lane] = dv;
            s_next[(s + 2) % 3][lane] = nv;
        }
        if (wrp == 0) {
            unsigned nx = s_next[cur][lane];
            unsigned keep = 0u;
            if (lane == 0) {
                unsigned d[32];
#pragma unroll
                for (int b = 0; b < 32; b++) d[b] = s_diag[cur][b];
                unsigned actb = ~(s_remv[s] | s_prio);
                int lim = KK - s * 32; if (lim > 32) lim = 32;
#pragma unroll 8
                for (int b = 0; b < 32; b++) {
                    if (b < lim && ((actb >> b) & 1u)) {
                        keep |= (1u << b);
                        actb &= ~d[b];
                    }
                }
                s_keep[s] = keep;
            }
            keep = __shfl_sync(0xffffffffu, keep, 0);
            unsigned v = ((keep >> lane) & 1u) ? nx : 0u;
#pragma unroll
            for (int o = 16; o > 0; o >>= 1) v |= __shfl_xor_sync(0xffffffffu, v, o);
            if (lane == 0) s_prio = v;
        }
        if (wrp >= 2 && s >= 1) {
            unsigned kp = s_keep[s - 1];
            if (kp) {
                int rbase = (s - 1) * 32;
                for (int wd = s + 1 + (t - 64); wd < NWRD; wd += 64) {
                    unsigned acc = 0u;
                    unsigned k2 = kp;
                    while (k2) {
                        int b0 = __ffs(k2) - 1; k2 &= k2 - 1;
                        int b1 = -1, b2 = -1, b3 = -1;
                        if (k2) { b1 = __ffs(k2) - 1; k2 &= k2 - 1; }
                        if (k2) { b2 = __ffs(k2) - 1; k2 &= k2 - 1; }
                        if (k2) { b3 = __ffs(k2) - 1; k2 &= k2 - 1; }
                        unsigned m0 = g_mask[(rbase + b0) * NWRD + wd];
                        unsigned m1 = (b1 >= 0) ? g_mask[(rbase + b1) * NWRD + wd] : 0u;
                        unsigned m2 = (b2 >= 0) ? g_mask[(rbase + b2) * NWRD + wd] : 0u;
                        unsigned m3 = (b3 >= 0) ? g_mask[(rbase + b3) * NWRD + wd] : 0u;
                        acc |= (m0 | m1) | (m2 | m3);
                    }
                    s_remv[wd] |= acc;
                }
            }
        }
        __syncthreads();
    }

    if (t == 0) {
        int s = 0;
        for (int w = 0; w < NWRD; w++) { pfx[w] = s; s += __popc(s_keep[w]); }
        pfx[NWRD] = s;
    }
    __syncthreads();
    if (t < NWRD) {
        unsigned kp = s_keep[t];
        int r = pfx[t];
        while (kp) {
            int b = __ffs(kp) - 1;
            kp &= kp - 1;
            int i = t * 32 + b;
            if (r < POST && g_ss[i] > -1e8f) {
                float4 bb = g_sb4[i];
                out[3 + r * 5 + 1] = bb.x;
                out[3 + r * 5 + 2] = bb.y;
                out[3 + r * 5 + 3] = bb.z;
                out[3 + r * 5 + 4] = bb.w;
            }
            r++;
        }
    }
}

// ---------------- anchor target ----------------
__global__ void k_target(const float* __restrict__ gtb) {
    __shared__ float cm[32 * 5];
    __shared__ float colmax[5];
    __shared__ int cnt0, cnt1;
    int t = threadIdx.x;  // 1024
    if (t == 0) { cnt0 = 0; cnt1 = 0; }
    float gx1[5], gy1[5], gx2[5], gy2[5], ga[5];
#pragma unroll
    for (int g = 0; g < 5; g++) {
        gx1[g] = gtb[g * 5 + 0]; gy1[g] = gtb[g * 5 + 1];
        gx2[g] = gtb[g * 5 + 2]; gy2[g] = gtb[g * 5 + 3];
        ga[g] = (gx2[g] - gx1[g] + 1.f) * (gy2[g] - gy1[g] + 1.f);
    }
    float pc[5] = {-FLT_MAX, -FLT_MAX, -FLT_MAX, -FLT_MAX, -FLT_MAX};
    for (int k = t; k < KK; k += 1024) {
        float ax1, ay1, ax2, ay2; bool ins;
        get_anchor(k, ax1, ay1, ax2, ay2, ins);
        float aa = (ax2 - ax1 + 1.f) * (ay2 - ay1 + 1.f);
        float best = -FLT_MAX; int bg = 0;
#pragma unroll
        for (int g = 0; g < 5; g++) {
            float xx1 = fmaxf(ax1, gx1[g]), yy1 = fmaxf(ay1, gy1[g]);
            float xx2 = fminf(ax2, gx2[g]), yy2 = fminf(ay2, gy2[g]);
            float iw = fmaxf(xx2 - xx1 + 1.f, 0.f);
            float ih = fmaxf(yy2 - yy1 + 1.f, 0.f);
            float inter = iw * ih;
            float ov = inter / (aa + ga[g] - inter);
            ov = ins ? ov : -1.f;
            g_ov[k * 5 + g] = ov;
            pc[g] = fmaxf(pc[g], ov);
            if (ov > best) { best = ov; bg = g; }
        }
        g_maxov[k] = best;
        g_arg[k] = bg;
    }
#pragma unroll
    for (int g = 0; g < 5; g++) {
        float v = pc[g];
#pragma unroll
        for (int o = 16; o > 0; o >>= 1) v = fmaxf(v, __shfl_down_sync(0xffffffffu, v, o));
        if ((t & 31) == 0) cm[(t >> 5) * 5 + g] = v;
    }
    __syncthreads();
    if (t < 5) {
        float v = -FLT_MAX;
        for (int wpi = 0; wpi < 32; wpi++) v = fmaxf(v, cm[wpi * 5 + t]);
        colmax[t] = v;
    }
    __syncthreads();
    for (int k = t; k < KK; k += 1024) {
        float ax1, ay1, ax2, ay2; bool ins;
        get_anchor(k, ax1, ay1, ax2, ay2, ins);
        float mo = g_maxov[k];
        int lab = -1;
        if (ins && mo < 0.3f) lab = 0;
        bool gb = false;
#pragma unroll
        for (int g = 0; g < 5; g++)
            if (g_ov[k * 5 + g] == colmax[g]) gb = true;
        if (gb && ins) lab = 1;
        if (ins && mo >= 0.7f) lab = 1;
        g_labels[k] = lab;
        if (lab >= 0) atomicAdd(&cnt0, 1);
        if (lab == 1) atomicAdd(&cnt1, 1);
    }
    __syncthreads();
    if (t == 0) { g_counts[0] = cnt0; g_counts[1] = cnt1; }
}

// ---------------- losses ----------------
__global__ void k_loss(const float* __restrict__ gtb, float* out) {
    __shared__ double red[32];
    int t = threadIdx.x;  // 1024
    int nex = g_counts[0], nfg = g_counts[1];
    float num_ex = (float)(nex > 1 ? nex : 1);
    double scls = 0.0, sbox = 0.0, sact = 0.0;

    for (int i = t; i < KK; i += 1024) {
        int a = i / 300, pos = i - a * 300;
        int lab = g_labels[pos * 12 + a];
        if (lab != -1) {
            float x0 = g_y2[a * 300 + pos], x1 = g_y2[(12 + a) * 300 + pos];
            float m = fmaxf(x0, x1);
            float lse = m + logf(expf(x0 - m) + expf(x1 - m));
            float xl = lab ? x1 : x0;
            scls += (double)(lse - xl);
        }
    }

    for (int e = t; e < 14400; e += 1024) {
        int ch = e / 300, pos = e - ch * 300;
        int a = ch >> 2, c = ch & 3;
        int k = pos * 12 + a;
        int lab = g_labels[k];
        float ow = (lab >= 0) ? (1.f / num_ex) : 0.f;
        float iw = (lab == 1) ? 1.f : 0.f;
        float ax1, ay1, ax2, ay2; bool ins;
        get_anchor(k, ax1, ay1, ax2, ay2, ins);
        float tgt = 0.f;
        if (ins) {
            int g = g_arg[k];
            float gx1 = gtb[g * 5 + 0], gy1 = gtb[g * 5 + 1];
            float gx2 = gtb[g * 5 + 2], gy2 = gtb[g * 5 + 3];
            float ew = ax2 - ax1 + 1.f, eh = ay2 - ay1 + 1.f;
            float ecx = ax1 + 0.5f * ew, ecy = ay1 + 0.5f * eh;
            float gw = gx2 - gx1 + 1.f, gh = gy2 - gy1 + 1.f;
            float gcx = gx1 + 0.5f * gw, gcy = gy1 + 0.5f * gh;
            float tv;
            if (c == 0) tv = (gcx - ecx) / ew;
            else if (c == 1) tv = (gcy - ecy) / eh;
            else if (c == 2) tv = logf(gw / ew);
            else tv = logf(gh / eh);
            tgt = tv;
        }
        float pred = g_y2[(24 + ch) * 300 + pos];
        float d = iw * (pred - tgt);
        float ad = fabsf(d);
        float loss = (ad < (1.f / 9.f)) ? (0.5f * 9.f * d * d) : (ad - 0.5f / 9.f);
        sbox += (double)(ow * loss);
    }

    int gl = (int)gtb[4];
    for (int i = t; i < KK; i += 1024) {
        int a = i / 300, pos = i - a * 300;
        if (g_labels[pos * 12 + a] == 1) {
            float sa[22];
            float mx = -FLT_MAX;
#pragma unroll
            for (int n = 0; n < 22; n++) {
                int idx = i * 22 + n;
                int ch = idx / 300, pp = idx - ch * 300;
                float v = g_y2[(72 + ch) * 300 + pp];
                float s = 1.f / (1.f + expf(-v));
                sa[n] = s;
                mx = fmaxf(mx, s);
            }
            float se = 0.f;
#pragma unroll
            for (int n = 0; n < 22; n++) se += expf(sa[n] - mx);
            sact += (double)(mx + logf(se) - sa[gl]);
        }
    }

    double rs = blk_sumd(scls, red, t);
    double rb = blk_sumd(sbox, red, t);
    double ra = blk_sumd(sact, red, t);
    if (t == 0) {
        out[0] = (float)((rs / (double)nex) / 8.0);
        out[1] = (float)(rb / 8.0);
        out[2] = (float)(ra / (double)nfg);
    }
}

// ---------------- launch ----------------
extern "C" void kernel_launch(void* const* d_in, const int* in_sizes, int n_in,
                              void* d_out, int out_size) {
    const float* x   = (const float*)d_in[0];
    const float* gtb = (const float*)d_in[1];
    const float* w1  = (const float*)d_in[3];
    const float* b1  = (const float*)d_in[4];
    const float* g1  = (const float*)d_in[5];
    const float* bb1 = (const float*)d_in[6];
    const float* w2  = (const float*)d_in[7];
    const float* b2  = (const float*)d_in[8];
    const float* g2  = (const float*)d_in[9];
    const float* bb2 = (const float*)d_in[10];
    float* out = (float*)d_out;

    // launch #4 is the ncu-captured slot -> k_sort profiled this round
    k_target<<<1, 1024>>>(gtb);                  // 1 (independent)
    k_conv1<<<256, 320>>>(x, w1, b1, g1, bb1);   // 2
    k_conv2<<<84, 640>>>(w2, b2, g2, bb2);       // 3
    k_sort<<<1, 1024>>>();                       // 4 (profiled)
    k_mask<<<113, 512>>>(out, out_size);         // 5
    k_scan<<<1, 128>>>(out);                     // 6
    k_loss<<<1, 1024>>>(gtb, out);               // 7
}

// round 15
// speedup vs baseline: 1.2349x; 1.2308x over previous
#include <cuda_runtime.h>
#include <math.h>
#include <float.h>

#define HH 15
#define WW 20
#define AA 12
#define KK 3600
#define NWRD 113      // ceil(3600/32)
#define POST 2000
#define NTILE 6441    // 113*114/2 upper-triangle 32x32 tiles
#define NWARPS_MASK 1808  // 113 blocks * 16 warps

// ---------------- scratch (no allocations allowed) ----------------
__device__ float    g_relu1[512*300];
__device__ float    g_y2[336*300];
__device__ float    g_boxes[KK*4];
__device__ float4   g_sb4[KK];
__device__ float    g_ss[KK];
__device__ float    g_areas[KK];
__device__ unsigned g_mask[KK*NWRD];
__device__ float    g_ov[KK*5];
__device__ float    g_maxov[KK];
__device__ int      g_arg[KK];
__device__ int      g_labels[KK];
__device__ int      g_counts[2];

// ---------------- packed f32x2 helpers (Blackwell) ----------------
__device__ __forceinline__ unsigned long long pk2(float lo, float hi) {
    unsigned long long r;
    asm("mov.b64 %0, {%1, %2};" : "=l"(r) : "f"(lo), "f"(hi));
    return r;
}
__device__ __forceinline__ void unpk2(unsigned long long v, float& lo, float& hi) {
    asm("mov.b64 {%0, %1}, %2;" : "=f"(lo), "=f"(hi) : "l"(v));
}
__device__ __forceinline__ void fma2(unsigned long long& d,
                                     unsigned long long a, unsigned long long b) {
    asm("fma.rn.f32x2 %0, %1, %2, %0;" : "+l"(d) : "l"(a), "l"(b));
}

// ---------------- helpers ----------------
__device__ __forceinline__ void get_anchor(int k, float& x1, float& y1,
                                           float& x2, float& y2, bool& ins) {
    int a = k % AA;  int pos = k / AA;
    int h = pos / WW, w = pos % WW;
    int r = a >> 2, s = a & 3;
    int wsi = (r == 0) ? 23 : ((r == 1) ? 16 : 11);
    int hsi = (r == 0) ? 12 : ((r == 1) ? 16 : 22);
    int scl = 4 << s;
    float wwf = (float)(wsi * scl), hhf = (float)(hsi * scl);
    float sx = (float)(w * 16), sy = (float)(h * 16);
    x1 = sx + 7.5f - 0.5f * (wwf - 1.f);
    y1 = sy + 7.5f - 0.5f * (hhf - 1.f);
    x2 = sx + 7.5f + 0.5f * (wwf - 1.f);
    y2 = sy + 7.5f + 0.5f * (hhf - 1.f);
    ins = (x1 >= 0.f) && (y1 >= 0.f) && (x2 < 320.f) && (y2 < 240.f);
}

template <int NWARP>
__device__ __forceinline__ float blk_sum(float v, float* red, int tid) {
#pragma unroll
    for (int o = 16; o > 0; o >>= 1) v += __shfl_down_sync(0xffffffffu, v, o);
    if ((tid & 31) == 0) red[tid >> 5] = v;
    __syncthreads();
    float s;
    if (tid == 0) { s = 0.f; for (int i = 0; i < NWARP; i++) s += red[i]; red[31] = s; }
    __syncthreads();
    s = red[31];
    __syncthreads();
    return s;
}

__device__ __forceinline__ double blk_sumd(double v, double* red, int tid) {
#pragma unroll
    for (int o = 16; o > 0; o >>= 1) v += __shfl_down_sync(0xffffffffu, v, o);
    if ((tid & 31) == 0) red[tid >> 5] = v;
    __syncthreads();
    double s;
    if (tid == 0) { s = 0.0; for (int i = 0; i < 32; i++) s += red[i]; red[0] = s; }
    __syncthreads();
    s = red[0];
    __syncthreads();
    return s;
}

// ---------------- conv1 3x3 (512->512) + BN(train) + ReLU ----------------
// grid 256, block 320. Block: 2 oc over 300 positions. Thread: 4 adjacent
// positions (75 groups). 4-way ic split: quarter q = tid/80 does icl q*4..+3
// (partials combined via smem). 8 fma2 chains; halved LDS bytes per FMA2.
__global__ void k_conv1(const float* __restrict__ x, const float* __restrict__ wgt,
                        const float* __restrict__ bias, const float* __restrict__ gg,
                        const float* __restrict__ bb) {
    __shared__ float xs[16 * 374];                // 16 ic x (17*22) padded
    __shared__ __align__(16) float ws[16 * 20];   // [icl][tap*2+ocl], pad 18->20
    __shared__ unsigned short sdst[4800];
    __shared__ float part[1800];                  // 3 quarters x 75 x 8
    __shared__ float red[32];
    int tid = threadIdx.x;     // 320
    int oc0 = blockIdx.x * 2;
    int q = tid / 80;
    int lt = tid - q * 80;
    bool act = lt < 75;
    int h = lt / 5;
    int cg = (lt % 5) * 4;
    int icl0 = q * 4;
    unsigned long long qa[4] = {0, 0, 0, 0};  // even taps, pos 0..3 ({oc0,oc1})
    unsigned long long qb[4] = {0, 0, 0, 0};  // odd taps

    for (int i = tid; i < 16 * 374; i += 320) xs[i] = 0.f;
    for (int i = tid; i < 4800; i += 320) {
        int icl = i / 300, p = i - icl * 300;
        sdst[i] = (unsigned short)(icl * 374 + (p / 20 + 1) * 22 + (p % 20 + 1));
    }
    __syncthreads();

    for (int cb = 0; cb < 32; cb++) {
        int icb = cb * 16;
        const float* xsrc = x + icb * 300;
#pragma unroll
        for (int i = tid; i < 4800; i += 320)
            xs[sdst[i]] = xsrc[i];
        if (tid < 288) {
            int icl = tid / 18, r = tid - icl * 18;
            int tap = r >> 1, ocl = r & 1;
            ws[icl * 20 + r] = wgt[(oc0 + ocl) * 4608 + (icb + icl) * 9 + tap];
        }
        __syncthreads();
        if (act) {
#pragma unroll
            for (int ii = 0; ii < 4; ii++) {
                int icl = icl0 + ii;
                const float* xp = &xs[icl * 374 + h * 22 + cg];
                float xv[3][6];
#pragma unroll
                for (int dh = 0; dh < 3; dh++) {
                    // base element offset even; +0/+2/+4 stay even -> LDS.64
                    unsigned long long p01 =
                        *(const unsigned long long*)(xp + dh * 22);
                    unsigned long long p23 =
                        *(const unsigned long long*)(xp + dh * 22 + 2);
                    unsigned long long p45 =
                        *(const unsigned long long*)(xp + dh * 22 + 4);
                    unpk2(p01, xv[dh][0], xv[dh][1]);
                    unpk2(p23, xv[dh][2], xv[dh][3]);
                    unpk2(p45, xv[dh][4], xv[dh][5]);
                }
                const float* wb = &ws[icl * 20];
                unsigned long long wt[9];
                {
                    ulonglong2 wA = *(const ulonglong2*)(wb);
                    ulonglong2 wB = *(const ulonglong2*)(wb + 4);
                    ulonglong2 wC = *(const ulonglong2*)(wb + 8);
                    ulonglong2 wD = *(const ulonglong2*)(wb + 12);
                    wt[0] = wA.x; wt[1] = wA.y; wt[2] = wB.x; wt[3] = wB.y;
                    wt[4] = wC.x; wt[5] = wC.y; wt[6] = wD.x; wt[7] = wD.y;
                    wt[8] = *(const unsigned long long*)(wb + 16);
                }
#pragma unroll
                for (int dh = 0; dh < 3; dh++)
#pragma unroll
                    for (int dw = 0; dw < 3; dw++) {
                        int tap = dh * 3 + dw;
                        unsigned long long w01 = wt[tap];
                        if (tap & 1) {
#pragma unroll
                            for (int p = 0; p < 4; p++)
                                fma2(qb[p], w01, pk2(xv[dh][dw + p], xv[dh][dw + p]));
                        } else {
#pragma unroll
                            for (int p = 0; p < 4; p++)
                                fma2(qa[p], w01, pk2(xv[dh][dw + p], xv[dh][dw + p]));
                        }
                    }
            }
        }
        __syncthreads();
    }

    // combine chains -> per-position oc0/oc1, then combine quarters
    float v0[4], v1[4];
#pragma unroll
    for (int p = 0; p < 4; p++) {
        float t0, t1, t2, t3;
        unpk2(qa[p], t0, t1);
        unpk2(qb[p], t2, t3);
        v0[p] = t0 + t2;   // oc0
        v1[p] = t1 + t3;   // oc1
    }
    if (act && q > 0) {
        int b = (q - 1) * 600 + lt * 8;
#pragma unroll
        for (int p = 0; p < 4; p++) {
            part[b + p] = v0[p];
            part[b + 4 + p] = v1[p];
        }
    }
    __syncthreads();
    bool actF = act && (q == 0);
    if (actF) {
#pragma unroll
        for (int g = 0; g < 3; g++) {
            int b = g * 600 + lt * 8;
#pragma unroll
            for (int p = 0; p < 4; p++) {
                v0[p] += part[b + p];
                v1[p] += part[b + 4 + p];
            }
        }
#pragma unroll
        for (int p = 0; p < 4; p++) {
            v0[p] += bias[oc0 + 0];
            v1[p] += bias[oc0 + 1];
        }
    }
    int p0 = actF ? (h * 20 + cg) : 0;
#define BN_OC(V, OCL)                                                                  \
    {                                                                                  \
        float m = blk_sum<10>(actF ? (V[0] + V[1] + V[2] + V[3]) : 0.f, red, tid)      \
                  / 300.f;                                                             \
        float d0 = V[0] - m, d1 = V[1] - m, d2 = V[2] - m, d3 = V[3] - m;              \
        float vv = blk_sum<10>(                                                        \
                       actF ? (d0 * d0 + d1 * d1 + d2 * d2 + d3 * d3) : 0.f, red, tid) \
                   / 300.f;                                                            \
        if (actF) {                                                                    \
            float rs = rsqrtf(vv + 1e-5f) * gg[oc0 + OCL];                             \
            float bbv = bb[oc0 + OCL];                                                 \
            g_relu1[(oc0 + OCL) * 300 + p0 + 0] = fmaxf(d0 * rs + bbv, 0.f);           \
            g_relu1[(oc0 + OCL) * 300 + p0 + 1] = fmaxf(d1 * rs + bbv, 0.f);           \
            g_relu1[(oc0 + OCL) * 300 + p0 + 2] = fmaxf(d2 * rs + bbv, 0.f);           \
            g_relu1[(oc0 + OCL) * 300 + p0 + 3] = fmaxf(d3 * rs + bbv, 0.f);           \
        }                                                                              \
    }
    BN_OC(v0, 0)
    BN_OC(v1, 1)
#undef BN_OC
}

// ---------------- conv2 1x1 (512->336) + BN(train) ----------------
// grid 84, block 640. 4 oc per block; 2-way ic split.
__global__ void k_conv2(const float* __restrict__ w2, const float* __restrict__ b2,
                        const float* __restrict__ g2, const float* __restrict__ bb2) {
    __shared__ __align__(16) float wst[2048];  // [ic][oc] for float4 loads
    __shared__ float part[300 * 4];
    __shared__ float red[32];
    int tid = threadIdx.x;     // 640
    int oc0 = blockIdx.x * 4;
    int half = tid / 320;      // warp-uniform
    int lt = tid - half * 320;
    for (int i = tid; i < 2048; i += 640) {
        int ic = i >> 2, ocl = i & 3;
        wst[i] = w2[(oc0 + ocl) * 512 + ic];
    }
    __syncthreads();
    bool act = lt < 300;
    float a0 = 0, a1 = 0, a2 = 0, a3 = 0;
    if (act) {
        int ic0 = half * 256;
#pragma unroll 8
        for (int ii = 0; ii < 256; ii++) {
            int ic = ic0 + ii;
            float rv = g_relu1[ic * 300 + lt];
            float4 wv = ((const float4*)wst)[ic];
            a0 += wv.x * rv; a1 += wv.y * rv; a2 += wv.z * rv; a3 += wv.w * rv;
        }
    }
    if (act && half == 1) {
        part[lt * 4 + 0] = a0; part[lt * 4 + 1] = a1;
        part[lt * 4 + 2] = a2; part[lt * 4 + 3] = a3;
    }
    __syncthreads();
    bool actF = act && (half == 0);
    if (actF) {
        a0 += part[lt * 4 + 0]; a1 += part[lt * 4 + 1];
        a2 += part[lt * 4 + 2]; a3 += part[lt * 4 + 3];
        a0 += b2[oc0 + 0]; a1 += b2[oc0 + 1]; a2 += b2[oc0 + 2]; a3 += b2[oc0 + 3];
    }
#define BN2_OC(A0, OCL)                                                         \
    {                                                                           \
        float m = blk_sum<20>(actF ? A0 : 0.f, red, tid) / 300.f;               \
        float d = A0 - m;                                                       \
        float vv = blk_sum<20>(actF ? d * d : 0.f, red, tid) / 300.f;           \
        if (actF) {                                                             \
            g_y2[(oc0 + OCL) * 300 + lt] =                                      \
                d * rsqrtf(vv + 1e-5f) * g2[oc0 + OCL] + bb2[oc0 + OCL];        \
        }                                                                       \
    }
    BN2_OC(a0, 0)
    BN2_OC(a1, 1)
    BN2_OC(a2, 2)
    BN2_OC(a3, 3)
#undef BN2_OC
}

// ---------------- fused props + u64 bitonic sort ----------------
__device__ __forceinline__ void cex64(unsigned long long& a, unsigned long long& b,
                                      bool asc) {
    bool sw = asc ? (a > b) : (a < b);
    if (sw) { unsigned long long t = a; a = b; b = t; }
}

__global__ void k_sort() {
    __shared__ unsigned long long sk[4096];
    int tid = threadIdx.x;  // 1024

    for (int k = tid; k < 4096; k += 1024) {
        float sc = -FLT_MAX;
        if (k < KK) {
            int a = k % AA, pos = k / AA;
            float ax1, ay1, ax2, ay2; bool ins;
            get_anchor(k, ax1, ay1, ax2, ay2, ins);
            float wA = ax2 - ax1 + 1.f, hA = ay2 - ay1 + 1.f;
            float cx = ax1 + 0.5f * wA, cy = ay1 + 0.5f * hA;
            float d0 = g_y2[(24 + 4 * a + 0) * 300 + pos];
            float d1 = g_y2[(24 + 4 * a + 1) * 300 + pos];
            float d2 = g_y2[(24 + 4 * a + 2) * 300 + pos];
            float d3 = g_y2[(24 + 4 * a + 3) * 300 + pos];
            float pcx = d0 * wA + cx, pcy = d1 * hA + cy;
            float pw = expf(d2) * wA, ph = expf(d3) * hA;
            float x1 = pcx - 0.5f * pw, y1 = pcy - 0.5f * ph;
            float x2 = pcx + 0.5f * pw, y2 = pcy + 0.5f * ph;
            x1 = fminf(fmaxf(x1, 0.f), 319.f);
            y1 = fminf(fmaxf(y1, 0.f), 239.f);
            x2 = fminf(fmaxf(x2, 0.f), 319.f);
            y2 = fminf(fmaxf(y2, 0.f), 239.f);
            float wsz = x2 - x1 + 1.f, hsz = y2 - y1 + 1.f;
            float c0 = g_y2[a * 300 + pos], c1 = g_y2[(AA + a) * 300 + pos];
            float mm = fmaxf(c0, c1);
            float e0 = expf(c0 - mm), e1 = expf(c1 - mm);
            sc = e1 / (e0 + e1);
            if (!((wsz >= 8.f) && (hsz >= 8.f))) sc = -1e9f;
            g_boxes[k * 4 + 0] = x1;
            g_boxes[k * 4 + 1] = y1;
            g_boxes[k * 4 + 2] = x2;
            g_boxes[k * 4 + 3] = y2;
        }
        unsigned u = __float_as_uint(sc);
        unsigned ou = (u & 0x80000000u) ? ~u : (u | 0x80000000u);
        sk[k] = ((unsigned long long)(~ou) << 32) | (unsigned)k;
    }
    __syncthreads();

    {
        int b4 = tid * 4;
        unsigned long long k0 = sk[b4], k1 = sk[b4 + 1],
                           k2 = sk[b4 + 2], k3 = sk[b4 + 3];
        cex64(k0, k1, true);
        cex64(k2, k3, false);
        bool d4 = ((b4 & 4) == 0);
        cex64(k0, k2, d4); cex64(k1, k3, d4);
        cex64(k0, k1, d4); cex64(k2, k3, d4);
        sk[b4] = k0; sk[b4 + 1] = k1; sk[b4 + 2] = k2; sk[b4 + 3] = k3;
    }
    __syncthreads();

    for (int size = 8; size <= 4096; size <<= 1) {
        for (int stride = size >> 1; stride >= 4; stride >>= 1) {
            for (int i = tid; i < 4096; i += 1024) {
                int j = i ^ stride;
                if (j > i) {
                    bool asc = ((i & size) == 0);
                    unsigned long long ki = sk[i], kj = sk[j];
                    bool sw = asc ? (ki > kj) : (ki < kj);
                    if (sw) { sk[i] = kj; sk[j] = ki; }
                }
            }
            __syncthreads();
        }
        {
            int b4 = tid * 4;
            unsigned long long k0 = sk[b4], k1 = sk[b4 + 1],
                               k2 = sk[b4 + 2], k3 = sk[b4 + 3];
            bool dd = ((b4 & size) == 0);
            cex64(k0, k2, dd); cex64(k1, k3, dd);
            cex64(k0, k1, dd); cex64(k2, k3, dd);
            sk[b4] = k0; sk[b4 + 1] = k1; sk[b4 + 2] = k2; sk[b4 + 3] = k3;
        }
        __syncthreads();
    }

    for (int i = tid; i < KK; i += 1024) {
        unsigned long long kk = sk[i];
        int v = (int)(kk & 0xFFFFFFFFu);
        unsigned ou = ~((unsigned)(kk >> 32));
        unsigned u = (ou & 0x80000000u) ? (ou & 0x7FFFFFFFu) : ~ou;
        g_ss[i] = __uint_as_float(u);
        float x1 = g_boxes[v * 4 + 0], y1 = g_boxes[v * 4 + 1];
        float x2 = g_boxes[v * 4 + 2], y2 = g_boxes[v * 4 + 3];
        g_sb4[i] = make_float4(x1, y1, x2, y2);
        g_areas[i] = (x2 - x1 + 1.f) * (y2 - y1 + 1.f);
    }
}

// ---------------- NMS suppression bitmask (warp-per-32x32-tile) --------------
__global__ void k_mask(float* out, int out_size) {
    for (int i = blockIdx.x * 512 + threadIdx.x; i < out_size; i += 113 * 512)
        out[i] = 0.f;
    int lane = threadIdx.x & 31;
    int gw = blockIdx.x * 16 + (threadIdx.x >> 5);
    for (int tile = gw; tile < NTILE; tile += NWARPS_MASK) {
        int rw = (int)(113.5f - sqrtf(113.5f * 113.5f - 2.f * (float)tile));
        if (rw < 0) rw = 0;
        while ((rw + 1) * 113 - ((rw + 1) * rw) / 2 <= tile) rw++;
        while (rw * 113 - (rw * (rw - 1)) / 2 > tile) rw--;
        int cw = rw + (tile - (rw * 113 - (rw * (rw - 1)) / 2));
        int j = cw * 32 + lane;
        float4 bj = make_float4(0, 0, 0, 0);
        float aj = 1.f;
        bool jv = (j < KK);
        if (jv) {
            bj = g_sb4[j];
            aj = (bj.z - bj.x + 1.f) * (bj.w - bj.y + 1.f);
        }
        int rbase = rw * 32;
        unsigned myword = 0u;
#pragma unroll 4
        for (int r = 0; r < 32; r++) {
            int i = rbase + r;
            bool hit = false;
            if (i < KK) {
                float4 bi = g_sb4[i];   // broadcast load
                float ai = (bi.z - bi.x + 1.f) * (bi.w - bi.y + 1.f);
                if (jv && j > i) {
                    float xx1 = fmaxf(bi.x, bj.x), yy1 = fmaxf(bi.y, bj.y);
                    float xx2 = fminf(bi.z, bj.z), yy2 = fminf(bi.w, bj.w);
                    float iw = fmaxf(xx2 - xx1 + 1.f, 0.f);
                    float ih = fmaxf(yy2 - yy1 + 1.f, 0.f);
                    float inter = iw * ih;
                    float iou = inter / (ai + aj - inter);
                    hit = (iou > 0.7f);
                }
            }
            unsigned m = __ballot_sync(0xffffffffu, hit);
            if (lane == r) myword = m;
        }
        int i = rbase + lane;
        if (i < KK) g_mask[i * NWRD + cw] = myword;
    }
}

// ---------------- pipelined NMS scan + roi emit ----------------
// 1 block, 256 threads: warp0 resolve+priority, warp1 prefetch, warps2-7 lazy OR.
__global__ void k_scan(float* out) {
    __shared__ unsigned s_remv[NWRD];
    __shared__ unsigned s_keep[NWRD];
    __shared__ unsigned s_diag[3][32];
    __shared__ unsigned s_next[3][32];
    __shared__ unsigned s_prio;
    __shared__ int pfx[NWRD + 1];
    int t = threadIdx.x;  // 256
    int lane = t & 31, wrp = t >> 5;
    if (t < NWRD) s_remv[t] = 0u;
    if (t == 0) s_prio = 0u;
    if (wrp == 1) {
        int i0 = lane;
        s_diag[0][lane] = g_mask[i0 * NWRD + 0];
        s_next[0][lane] = g_mask[i0 * NWRD + 1];
        int i1 = 32 + lane;
        s_diag[1][lane] = g_mask[i1 * NWRD + 1];
        s_next[1][lane] = g_mask[i1 * NWRD + 2];
    }
    __syncthreads();

    for (int s = 0; s < NWRD; s++) {
        int cur = s % 3;
        if (wrp == 1 && s + 2 < NWRD) {
            int i = (s + 2) * 32 + lane;
            unsigned dv = 0u, nv = 0u;
            if (i < KK) {
                dv = g_mask[i * NWRD + (s + 2)];
                if (s + 3 < NWRD) nv = g_mask[i * NWRD + (s + 3)];
            }
            s_diag[(s + 2) % 3][lane] = dv;
            s_next[(s + 2) % 3][lane] = nv;
        }
        if (wrp == 0) {
            unsigned nx = s_next[cur][lane];
            unsigned keep = 0u;
            if (lane == 0) {
                unsigned d[32];
#pragma unroll
                for (int b = 0; b < 32; b++) d[b] = s_diag[cur][b];
                unsigned actb = ~(s_remv[s] | s_prio);
                int lim = KK - s * 32; if (lim > 32) lim = 32;
#pragma unroll 8
                for (int b = 0; b < 32; b++) {
                    if (b < lim && ((actb >> b) & 1u)) {
                        keep |= (1u << b);
                        actb &= ~d[b];
                    }
                }
                s_keep[s] = keep;
            }
            keep = __shfl_sync(0xffffffffu, keep, 0);
            unsigned v = ((keep >> lane) & 1u) ? nx : 0u;
#pragma unroll
            for (int o = 16; o > 0; o >>= 1) v |= __shfl_xor_sync(0xffffffffu, v, o);
            if (lane == 0) s_prio = v;
        }
        if (wrp >= 2 && s >= 1) {
            unsigned kp = s_keep[s - 1];
            if (kp) {
                int rbase = (s - 1) * 32;
                for (int wd = s + 1 + (t - 64); wd < NWRD; wd += 192) {
                    unsigned acc = 0u;
                    unsigned k2 = kp;
                    while (k2) {
                        int b0 = __ffs(k2) - 1; k2 &= k2 - 1;
                        int b1 = -1, b2 = -1, b3 = -1;
                        if (k2) { b1 = __ffs(k2) - 1; k2 &= k2 - 1; }
                        if (k2) { b2 = __ffs(k2) - 1; k2 &= k2 - 1; }
                        if (k2) { b3 = __ffs(k2) - 1; k2 &= k2 - 1; }
                        unsigned m0 = g_mask[(rbase + b0) * NWRD + wd];
                        unsigned m1 = (b1 >= 0) ? g_mask[(rbase + b1) * NWRD + wd] : 0u;
                        unsigned m2 = (b2 >= 0) ? g_mask[(rbase + b2) * NWRD + wd] : 0u;
                        unsigned m3 = (b3 >= 0) ? g_mask[(rbase + b3) * NWRD + wd] : 0u;
                        acc |= (m0 | m1) | (m2 | m3);
                    }
                    s_remv[wd] |= acc;
                }
            }
        }
        __syncthreads();
    }

    if (t == 0) {
        int s = 0;
        for (int w = 0; w < NWRD; w++) { pfx[w] = s; s += __popc(s_keep[w]); }
        pfx[NWRD] = s;
    }
    __syncthreads();
    if (t < NWRD) {
        unsigned kp = s_keep[t];
        int r = pfx[t];
        while (kp) {
            int b = __ffs(kp) - 1;
            kp &= kp - 1;
            int i = t * 32 + b;
            if (r < POST && g_ss[i] > -1e8f) {
                float4 bb = g_sb4[i];
                out[3 + r * 5 + 1] = bb.x;
                out[3 + r * 5 + 2] = bb.y;
                out[3 + r * 5 + 3] = bb.z;
                out[3 + r * 5 + 4] = bb.w;
            }
            r++;
        }
    }
}

// ---------------- fused anchor target + losses ----------------
__global__ void k_tl(const float* __restrict__ gtb, float* out) {
    __shared__ float cm[32 * 5];
    __shared__ float colmax[5];
    __shared__ int cnt0, cnt1;
    __shared__ double redd[32];
    int t = threadIdx.x;  // 1024
    if (t == 0) { cnt0 = 0; cnt1 = 0; }
    float gx1[5], gy1[5], gx2[5], gy2[5], ga[5];
#pragma unroll
    for (int g = 0; g < 5; g++) {
        gx1[g] = gtb[g * 5 + 0]; gy1[g] = gtb[g * 5 + 1];
        gx2[g] = gtb[g * 5 + 2]; gy2[g] = gtb[g * 5 + 3];
        ga[g] = (gx2[g] - gx1[g] + 1.f) * (gy2[g] - gy1[g] + 1.f);
    }
    float pc[5] = {-FLT_MAX, -FLT_MAX, -FLT_MAX, -FLT_MAX, -FLT_MAX};
    __syncthreads();
    for (int k = t; k < KK; k += 1024) {
        float ax1, ay1, ax2, ay2; bool ins;
        get_anchor(k, ax1, ay1, ax2, ay2, ins);
        float aa = (ax2 - ax1 + 1.f) * (ay2 - ay1 + 1.f);
        float best = -FLT_MAX; int bg = 0;
#pragma unroll
        for (int g = 0; g < 5; g++) {
            float xx1 = fmaxf(ax1, gx1[g]), yy1 = fmaxf(ay1, gy1[g]);
            float xx2 = fminf(ax2, gx2[g]), yy2 = fminf(ay2, gy2[g]);
            float iw = fmaxf(xx2 - xx1 + 1.f, 0.f);
            float ih = fmaxf(yy2 - yy1 + 1.f, 0.f);
            float inter = iw * ih;
            float ov = inter / (aa + ga[g] - inter);
            ov = ins ? ov : -1.f;
            g_ov[k * 5 + g] = ov;
            pc[g] = fmaxf(pc[g], ov);
            if (ov > best) { best = ov; bg = g; }
        }
        g_maxov[k] = best;
        g_arg[k] = bg;
    }
#pragma unroll
    for (int g = 0; g < 5; g++) {
        float v = pc[g];
#pragma unroll
        for (int o = 16; o > 0; o >>= 1) v = fmaxf(v, __shfl_down_sync(0xffffffffu, v, o));
        if ((t & 31) == 0) cm[(t >> 5) * 5 + g] = v;
    }
    __syncthreads();
    if (t < 5) {
        float v = -FLT_MAX;
        for (int wpi = 0; wpi < 32; wpi++) v = fmaxf(v, cm[wpi * 5 + t]);
        colmax[t] = v;
    }
    __syncthreads();
    for (int k = t; k < KK; k += 1024) {
        float ax1, ay1, ax2, ay2; bool ins;
        get_anchor(k, ax1, ay1, ax2, ay2, ins);
        float mo = g_maxov[k];
        int lab = -1;
        if (ins && mo < 0.3f) lab = 0;
        bool gb = false;
#pragma unroll
        for (int g = 0; g < 5; g++)
            if (g_ov[k * 5 + g] == colmax[g]) gb = true;
        if (gb && ins) lab = 1;
        if (ins && mo >= 0.7f) lab = 1;
        g_labels[k] = lab;
        if (lab >= 0) atomicAdd(&cnt0, 1);
        if (lab == 1) atomicAdd(&cnt1, 1);
    }
    __syncthreads();

    // ---------- loss phase ----------
    int nex = cnt0, nfg = cnt1;
    float num_ex = (float)(nex > 1 ? nex : 1);
    double scls = 0.0, sbox = 0.0, sact = 0.0;

    for (int i = t; i < KK; i += 1024) {
        int a = i / 300, pos = i - a * 300;
        int lab = g_labels[pos * 12 + a];
        if (lab != -1) {
            float x0 = g_y2[a * 300 + pos], x1 = g_y2[(12 + a) * 300 + pos];
            float m = fmaxf(x0, x1);
            float lse = m + logf(expf(x0 - m) + expf(x1 - m));
            float xl = lab ? x1 : x0;
            scls += (double)(lse - xl);
        }
    }

    for (int e = t; e < 14400; e += 1024) {
        int ch = e / 300, pos = e - ch * 300;
        int a = ch >> 2, c = ch & 3;
        int k = pos * 12 + a;
        int lab = g_labels[k];
        float ow = (lab >= 0) ? (1.f / num_ex) : 0.f;
        float iw = (lab == 1) ? 1.f : 0.f;
        float ax1, ay1, ax2, ay2; bool ins;
        get_anchor(k, ax1, ay1, ax2, ay2, ins);
        float tgt = 0.f;
        if (ins) {
            int g = g_arg[k];
            float gx1v = gtb[g * 5 + 0], gy1v = gtb[g * 5 + 1];
            float gx2v = gtb[g * 5 + 2], gy2v = gtb[g * 5 + 3];
            float ew = ax2 - ax1 + 1.f, eh = ay2 - ay1 + 1.f;
            float ecx = ax1 + 0.5f * ew, ecy = ay1 + 0.5f * eh;
            float gw = gx2v - gx1v + 1.f, gh = gy2v - gy1v + 1.f;
            float gcx = gx1v + 0.5f * gw, gcy = gy1v + 0.5f * gh;
            float tv;
            if (c == 0) tv = (gcx - ecx) / ew;
            else if (c == 1) tv = (gcy - ecy) / eh;
            else if (c == 2) tv = logf(gw / ew);
            else tv = logf(gh / eh);
            tgt = tv;
        }
        float pred = g_y2[(24 + ch) * 300 + pos];
        float d = iw * (pred - tgt);
        float ad = fabsf(d);
        float loss = (ad < (1.f / 9.f)) ? (0.5f * 9.f * d * d) : (ad - 0.5f / 9.f);
        sbox += (double)(ow * loss);
    }

    int gl = (int)gtb[4];
    for (int i = t; i < KK; i += 1024) {
        int a = i / 300, pos = i - a * 300;
        if (g_labels[pos * 12 + a] == 1) {
            float sa[22];
            float mx = -FLT_MAX;
#pragma unroll
            for (int n = 0; n < 22; n++) {
                int idx = i * 22 + n;
                int ch = idx / 300, pp = idx - ch * 300;
                float v = g_y2[(72 + ch) * 300 + pp];
                float s = 1.f / (1.f + expf(-v));
                sa[n] = s;
                mx = fmaxf(mx, s);
            }
            float se = 0.f;
#pragma unroll
            for (int n = 0; n < 22; n++) se += expf(sa[n] - mx);
            sact += (double)(mx + logf(se) - sa[gl]);
        }
    }

    double rs = blk_sumd(scls, redd, t);
    double rb = blk_sumd(sbox, redd, t);
    double ra = blk_sumd(sact, redd, t);
    if (t == 0) {
        out[0] = (float)((rs / (double)nex) / 8.0);
        out[1] = (float)(rb / 8.0);
        out[2] = (float)(ra / (double)nfg);
    }
}

// ---------------- launch ----------------
extern "C" void kernel_launch(void* const* d_in, const int* in_sizes, int n_in,
                              void* d_out, int out_size) {
    const float* x   = (const float*)d_in[0];
    const float* gtb = (const float*)d_in[1];
    const float* w1  = (const float*)d_in[3];
    const float* b1  = (const float*)d_in[4];
    const float* g1  = (const float*)d_in[5];
    const float* bb1 = (const float*)d_in[6];
    const float* w2  = (const float*)d_in[7];
    const float* b2  = (const float*)d_in[8];
    const float* g2  = (const float*)d_in[9];
    const float* bb2 = (const float*)d_in[10];
    float* out = (float*)d_out;

    k_conv1<<<256, 320>>>(x, w1, b1, g1, bb1);   // 1
    k_conv2<<<84, 640>>>(w2, b2, g2, bb2);       // 2
    k_sort<<<1, 1024>>>();                       // 3
    k_mask<<<113, 512>>>(out, out_size);         // 4 (profiled)
    k_scan<<<1, 256>>>(out);                     // 5
    k_tl<<<1, 1024>>>(gtb, out);                 // 6
}

// round 16
// speedup vs baseline: 1.2976x; 1.0508x over previous
#include <cuda_runtime.h>
#include <math.h>
#include <float.h>

#define HH 15
#define WW 20
#define AA 12
#define KK 3600
#define NWRD 113      // ceil(3600/32)
#define POST 2000
#define NTILE 6441    // 113*114/2 upper-triangle 32x32 tiles
#define NWARPS_MASK 2368  // 148 blocks * 16 warps

// ---------------- scratch (no allocations allowed) ----------------
__device__ float    g_relu1[512*300];
__device__ float    g_y2[336*300];
__device__ float    g_boxes[KK*4];
__device__ float4   g_sb4[KK];
__device__ float    g_ss[KK];
__device__ float    g_areas[KK];
__device__ unsigned g_mask[KK*NWRD];
__device__ float    g_ov[KK*5];
__device__ float    g_maxov[KK];
__device__ int      g_arg[KK];
__device__ int      g_labels[KK];
__device__ int      g_counts[2];

// ---------------- packed f32x2 helpers (Blackwell) ----------------
__device__ __forceinline__ unsigned long long pk2(float lo, float hi) {
    unsigned long long r;
    asm("mov.b64 %0, {%1, %2};" : "=l"(r) : "f"(lo), "f"(hi));
    return r;
}
__device__ __forceinline__ void unpk2(unsigned long long v, float& lo, float& hi) {
    asm("mov.b64 {%0, %1}, %2;" : "=f"(lo), "=f"(hi) : "l"(v));
}
__device__ __forceinline__ void fma2(unsigned long long& d,
                                     unsigned long long a, unsigned long long b) {
    asm("fma.rn.f32x2 %0, %1, %2, %0;" : "+l"(d) : "l"(a), "l"(b));
}

// ---------------- helpers ----------------
__device__ __forceinline__ void get_anchor(int k, float& x1, float& y1,
                                           float& x2, float& y2, bool& ins) {
    int a = k % AA;  int pos = k / AA;
    int h = pos / WW, w = pos % WW;
    int r = a >> 2, s = a & 3;
    int wsi = (r == 0) ? 23 : ((r == 1) ? 16 : 11);
    int hsi = (r == 0) ? 12 : ((r == 1) ? 16 : 22);
    int scl = 4 << s;
    float wwf = (float)(wsi * scl), hhf = (float)(hsi * scl);
    float sx = (float)(w * 16), sy = (float)(h * 16);
    x1 = sx + 7.5f - 0.5f * (wwf - 1.f);
    y1 = sy + 7.5f - 0.5f * (hhf - 1.f);
    x2 = sx + 7.5f + 0.5f * (wwf - 1.f);
    y2 = sy + 7.5f + 0.5f * (hhf - 1.f);
    ins = (x1 >= 0.f) && (y1 >= 0.f) && (x2 < 320.f) && (y2 < 240.f);
}

template <int NWARP>
__device__ __forceinline__ float blk_sum(float v, float* red, int tid) {
#pragma unroll
    for (int o = 16; o > 0; o >>= 1) v += __shfl_down_sync(0xffffffffu, v, o);
    if ((tid & 31) == 0) red[tid >> 5] = v;
    __syncthreads();
    float s;
    if (tid == 0) { s = 0.f; for (int i = 0; i < NWARP; i++) s += red[i]; red[31] = s; }
    __syncthreads();
    s = red[31];
    __syncthreads();
    return s;
}

__device__ __forceinline__ double blk_sumd(double v, double* red, int tid) {
#pragma unroll
    for (int o = 16; o > 0; o >>= 1) v += __shfl_down_sync(0xffffffffu, v, o);
    if ((tid & 31) == 0) red[tid >> 5] = v;
    __syncthreads();
    double s;
    if (tid == 0) { s = 0.0; for (int i = 0; i < 32; i++) s += red[i]; red[0] = s; }
    __syncthreads();
    s = red[0];
    __syncthreads();
    return s;
}

// ---------------- conv1 3x3 (512->512) + BN(train) + ReLU ----------------
// grid 256, block 320. Thread: 4 adjacent positions; 4-way ic split.
__global__ void k_conv1(const float* __restrict__ x, const float* __restrict__ wgt,
                        const float* __restrict__ bias, const float* __restrict__ gg,
                        const float* __restrict__ bb) {
    __shared__ float xs[16 * 374];                // 16 ic x (17*22) padded
    __shared__ __align__(16) float ws[16 * 20];   // [icl][tap*2+ocl], pad 18->20
    __shared__ unsigned short sdst[4800];
    __shared__ float part[1800];                  // 3 quarters x 75 x 8
    __shared__ float red[32];
    int tid = threadIdx.x;     // 320
    int oc0 = blockIdx.x * 2;
    int q = tid / 80;
    int lt = tid - q * 80;
    bool act = lt < 75;
    int h = lt / 5;
    int cg = (lt % 5) * 4;
    int icl0 = q * 4;
    unsigned long long qa[4] = {0, 0, 0, 0};
    unsigned long long qb[4] = {0, 0, 0, 0};

    for (int i = tid; i < 16 * 374; i += 320) xs[i] = 0.f;
    for (int i = tid; i < 4800; i += 320) {
        int icl = i / 300, p = i - icl * 300;
        sdst[i] = (unsigned short)(icl * 374 + (p / 20 + 1) * 22 + (p % 20 + 1));
    }
    __syncthreads();

    for (int cb = 0; cb < 32; cb++) {
        int icb = cb * 16;
        const float* xsrc = x + icb * 300;
#pragma unroll
        for (int i = tid; i < 4800; i += 320)
            xs[sdst[i]] = xsrc[i];
        if (tid < 288) {
            int icl = tid / 18, r = tid - icl * 18;
            int tap = r >> 1, ocl = r & 1;
            ws[icl * 20 + r] = wgt[(oc0 + ocl) * 4608 + (icb + icl) * 9 + tap];
        }
        __syncthreads();
        if (act) {
#pragma unroll
            for (int ii = 0; ii < 4; ii++) {
                int icl = icl0 + ii;
                const float* xp = &xs[icl * 374 + h * 22 + cg];
                float xv[3][6];
#pragma unroll
                for (int dh = 0; dh < 3; dh++) {
                    unsigned long long p01 =
                        *(const unsigned long long*)(xp + dh * 22);
                    unsigned long long p23 =
                        *(const unsigned long long*)(xp + dh * 22 + 2);
                    unsigned long long p45 =
                        *(const unsigned long long*)(xp + dh * 22 + 4);
                    unpk2(p01, xv[dh][0], xv[dh][1]);
                    unpk2(p23, xv[dh][2], xv[dh][3]);
                    unpk2(p45, xv[dh][4], xv[dh][5]);
                }
                const float* wb = &ws[icl * 20];
                unsigned long long wt[9];
                {
                    ulonglong2 wA = *(const ulonglong2*)(wb);
                    ulonglong2 wB = *(const ulonglong2*)(wb + 4);
                    ulonglong2 wC = *(const ulonglong2*)(wb + 8);
                    ulonglong2 wD = *(const ulonglong2*)(wb + 12);
                    wt[0] = wA.x; wt[1] = wA.y; wt[2] = wB.x; wt[3] = wB.y;
                    wt[4] = wC.x; wt[5] = wC.y; wt[6] = wD.x; wt[7] = wD.y;
                    wt[8] = *(const unsigned long long*)(wb + 16);
                }
#pragma unroll
                for (int dh = 0; dh < 3; dh++)
#pragma unroll
                    for (int dw = 0; dw < 3; dw++) {
                        int tap = dh * 3 + dw;
                        unsigned long long w01 = wt[tap];
                        if (tap & 1) {
#pragma unroll
                            for (int p = 0; p < 4; p++)
                                fma2(qb[p], w01, pk2(xv[dh][dw + p], xv[dh][dw + p]));
                        } else {
#pragma unroll
                            for (int p = 0; p < 4; p++)
                                fma2(qa[p], w01, pk2(xv[dh][dw + p], xv[dh][dw + p]));
                        }
                    }
            }
        }
        __syncthreads();
    }

    float v0[4], v1[4];
#pragma unroll
    for (int p = 0; p < 4; p++) {
        float t0, t1, t2, t3;
        unpk2(qa[p], t0, t1);
        unpk2(qb[p], t2, t3);
        v0[p] = t0 + t2;
        v1[p] = t1 + t3;
    }
    if (act && q > 0) {
        int b = (q - 1) * 600 + lt * 8;
#pragma unroll
        for (int p = 0; p < 4; p++) {
            part[b + p] = v0[p];
            part[b + 4 + p] = v1[p];
        }
    }
    __syncthreads();
    bool actF = act && (q == 0);
    if (actF) {
#pragma unroll
        for (int g = 0; g < 3; g++) {
            int b = g * 600 + lt * 8;
#pragma unroll
            for (int p = 0; p < 4; p++) {
                v0[p] += part[b + p];
                v1[p] += part[b + 4 + p];
            }
        }
#pragma unroll
        for (int p = 0; p < 4; p++) {
            v0[p] += bias[oc0 + 0];
            v1[p] += bias[oc0 + 1];
        }
    }
    int p0 = actF ? (h * 20 + cg) : 0;
#define BN_OC(V, OCL)                                                                  \
    {                                                                                  \
        float m = blk_sum<10>(actF ? (V[0] + V[1] + V[2] + V[3]) : 0.f, red, tid)      \
                  / 300.f;                                                             \
        float d0 = V[0] - m, d1 = V[1] - m, d2 = V[2] - m, d3 = V[3] - m;              \
        float vv = blk_sum<10>(                                                        \
                       actF ? (d0 * d0 + d1 * d1 + d2 * d2 + d3 * d3) : 0.f, red, tid) \
                   / 300.f;                                                            \
        if (actF) {                                                                    \
            float rs = rsqrtf(vv + 1e-5f) * gg[oc0 + OCL];                             \
            float bbv = bb[oc0 + OCL];                                                 \
            g_relu1[(oc0 + OCL) * 300 + p0 + 0] = fmaxf(d0 * rs + bbv, 0.f);           \
            g_relu1[(oc0 + OCL) * 300 + p0 + 1] = fmaxf(d1 * rs + bbv, 0.f);           \
            g_relu1[(oc0 + OCL) * 300 + p0 + 2] = fmaxf(d2 * rs + bbv, 0.f);           \
            g_relu1[(oc0 + OCL) * 300 + p0 + 3] = fmaxf(d3 * rs + bbv, 0.f);           \
        }                                                                              \
    }
    BN_OC(v0, 0)
    BN_OC(v1, 1)
#undef BN_OC
}

// ---------------- conv2 1x1 (512->336) + BN(train) ----------------
__global__ void k_conv2(const float* __restrict__ w2, const float* __restrict__ b2,
                        const float* __restrict__ g2, const float* __restrict__ bb2) {
    __shared__ __align__(16) float wst[2048];
    __shared__ float part[300 * 4];
    __shared__ float red[32];
    int tid = threadIdx.x;     // 640
    int oc0 = blockIdx.x * 4;
    int half = tid / 320;
    int lt = tid - half * 320;
    for (int i = tid; i < 2048; i += 640) {
        int ic = i >> 2, ocl = i & 3;
        wst[i] = w2[(oc0 + ocl) * 512 + ic];
    }
    __syncthreads();
    bool act = lt < 300;
    float a0 = 0, a1 = 0, a2 = 0, a3 = 0;
    if (act) {
        int ic0 = half * 256;
#pragma unroll 8
        for (int ii = 0; ii < 256; ii++) {
            int ic = ic0 + ii;
            float rv = g_relu1[ic * 300 + lt];
            float4 wv = ((const float4*)wst)[ic];
            a0 += wv.x * rv; a1 += wv.y * rv; a2 += wv.z * rv; a3 += wv.w * rv;
        }
    }
    if (act && half == 1) {
        part[lt * 4 + 0] = a0; part[lt * 4 + 1] = a1;
        part[lt * 4 + 2] = a2; part[lt * 4 + 3] = a3;
    }
    __syncthreads();
    bool actF = act && (half == 0);
    if (actF) {
        a0 += part[lt * 4 + 0]; a1 += part[lt * 4 + 1];
        a2 += part[lt * 4 + 2]; a3 += part[lt * 4 + 3];
        a0 += b2[oc0 + 0]; a1 += b2[oc0 + 1]; a2 += b2[oc0 + 2]; a3 += b2[oc0 + 3];
    }
#define BN2_OC(A0, OCL)                                                         \
    {                                                                           \
        float m = blk_sum<20>(actF ? A0 : 0.f, red, tid) / 300.f;               \
        float d = A0 - m;                                                       \
        float vv = blk_sum<20>(actF ? d * d : 0.f, red, tid) / 300.f;           \
        if (actF) {                                                             \
            g_y2[(oc0 + OCL) * 300 + lt] =                                      \
                d * rsqrtf(vv + 1e-5f) * g2[oc0 + OCL] + bb2[oc0 + OCL];        \
        }                                                                       \
    }
    BN2_OC(a0, 0)
    BN2_OC(a1, 1)
    BN2_OC(a2, 2)
    BN2_OC(a3, 3)
#undef BN2_OC
}

// ---------------- fused props + u64 bitonic sort ----------------
__device__ __forceinline__ void cex64(unsigned long long& a, unsigned long long& b,
                                      bool asc) {
    bool sw = asc ? (a > b) : (a < b);
    if (sw) { unsigned long long t = a; a = b; b = t; }
}

__global__ void k_sort() {
    __shared__ unsigned long long sk[4096];
    int tid = threadIdx.x;  // 1024

    for (int k = tid; k < 4096; k += 1024) {
        float sc = -FLT_MAX;
        if (k < KK) {
            int a = k % AA, pos = k / AA;
            float ax1, ay1, ax2, ay2; bool ins;
            get_anchor(k, ax1, ay1, ax2, ay2, ins);
            float wA = ax2 - ax1 + 1.f, hA = ay2 - ay1 + 1.f;
            float cx = ax1 + 0.5f * wA, cy = ay1 + 0.5f * hA;
            float d0 = g_y2[(24 + 4 * a + 0) * 300 + pos];
            float d1 = g_y2[(24 + 4 * a + 1) * 300 + pos];
            float d2 = g_y2[(24 + 4 * a + 2) * 300 + pos];
            float d3 = g_y2[(24 + 4 * a + 3) * 300 + pos];
            float pcx = d0 * wA + cx, pcy = d1 * hA + cy;
            float pw = expf(d2) * wA, ph = expf(d3) * hA;
            float x1 = pcx - 0.5f * pw, y1 = pcy - 0.5f * ph;
            float x2 = pcx + 0.5f * pw, y2 = pcy + 0.5f * ph;
            x1 = fminf(fmaxf(x1, 0.f), 319.f);
            y1 = fminf(fmaxf(y1, 0.f), 239.f);
            x2 = fminf(fmaxf(x2, 0.f), 319.f);
            y2 = fminf(fmaxf(y2, 0.f), 239.f);
            float wsz = x2 - x1 + 1.f, hsz = y2 - y1 + 1.f;
            float c0 = g_y2[a * 300 + pos], c1 = g_y2[(AA + a) * 300 + pos];
            float mm = fmaxf(c0, c1);
            float e0 = expf(c0 - mm), e1 = expf(c1 - mm);
            sc = e1 / (e0 + e1);
            if (!((wsz >= 8.f) && (hsz >= 8.f))) sc = -1e9f;
            g_boxes[k * 4 + 0] = x1;
            g_boxes[k * 4 + 1] = y1;
            g_boxes[k * 4 + 2] = x2;
            g_boxes[k * 4 + 3] = y2;
        }
        unsigned u = __float_as_uint(sc);
        unsigned ou = (u & 0x80000000u) ? ~u : (u | 0x80000000u);
        sk[k] = ((unsigned long long)(~ou) << 32) | (unsigned)k;
    }
    __syncthreads();

    {
        int b4 = tid * 4;
        unsigned long long k0 = sk[b4], k1 = sk[b4 + 1],
                           k2 = sk[b4 + 2], k3 = sk[b4 + 3];
        cex64(k0, k1, true);
        cex64(k2, k3, false);
        bool d4 = ((b4 & 4) == 0);
        cex64(k0, k2, d4); cex64(k1, k3, d4);
        cex64(k0, k1, d4); cex64(k2, k3, d4);
        sk[b4] = k0; sk[b4 + 1] = k1; sk[b4 + 2] = k2; sk[b4 + 3] = k3;
    }
    __syncthreads();

    for (int size = 8; size <= 4096; size <<= 1) {
        for (int stride = size >> 1; stride >= 4; stride >>= 1) {
            for (int i = tid; i < 4096; i += 1024) {
                int j = i ^ stride;
                if (j > i) {
                    bool asc = ((i & size) == 0);
                    unsigned long long ki = sk[i], kj = sk[j];
                    bool sw = asc ? (ki > kj) : (ki < kj);
                    if (sw) { sk[i] = kj; sk[j] = ki; }
                }
            }
            __syncthreads();
        }
        {
            int b4 = tid * 4;
            unsigned long long k0 = sk[b4], k1 = sk[b4 + 1],
                               k2 = sk[b4 + 2], k3 = sk[b4 + 3];
            bool dd = ((b4 & size) == 0);
            cex64(k0, k2, dd); cex64(k1, k3, dd);
            cex64(k0, k1, dd); cex64(k2, k3, dd);
            sk[b4] = k0; sk[b4 + 1] = k1; sk[b4 + 2] = k2; sk[b4 + 3] = k3;
        }
        __syncthreads();
    }

    for (int i = tid; i < KK; i += 1024) {
        unsigned long long kk = sk[i];
        int v = (int)(kk & 0xFFFFFFFFu);
        unsigned ou = ~((unsigned)(kk >> 32));
        unsigned u = (ou & 0x80000000u) ? (ou & 0x7FFFFFFFu) : ~ou;
        g_ss[i] = __uint_as_float(u);
        float x1 = g_boxes[v * 4 + 0], y1 = g_boxes[v * 4 + 1];
        float x2 = g_boxes[v * 4 + 2], y2 = g_boxes[v * 4 + 3];
        g_sb4[i] = make_float4(x1, y1, x2, y2);
        g_areas[i] = (x2 - x1 + 1.f) * (y2 - y1 + 1.f);
    }
}

// ---------------- NMS suppression bitmask (warp-per-32x32-tile) --------------
// grid 148 (1 block/SM), block 512.
__global__ void k_mask(float* out, int out_size) {
    for (int i = blockIdx.x * 512 + threadIdx.x; i < out_size; i += 148 * 512)
        out[i] = 0.f;
    int lane = threadIdx.x & 31;
    int gw = blockIdx.x * 16 + (threadIdx.x >> 5);
    for (int tile = gw; tile < NTILE; tile += NWARPS_MASK) {
        int rw = (int)(113.5f - sqrtf(113.5f * 113.5f - 2.f * (float)tile));
        if (rw < 0) rw = 0;
        while ((rw + 1) * 113 - ((rw + 1) * rw) / 2 <= tile) rw++;
        while (rw * 113 - (rw * (rw - 1)) / 2 > tile) rw--;
        int cw = rw + (tile - (rw * 113 - (rw * (rw - 1)) / 2));
        int j = cw * 32 + lane;
        float4 bj = make_float4(0, 0, 0, 0);
        float aj = 1.f;
        bool jv = (j < KK);
        if (jv) {
            bj = g_sb4[j];
            aj = (bj.z - bj.x + 1.f) * (bj.w - bj.y + 1.f);
        }
        int rbase = rw * 32;
        unsigned myword = 0u;
#pragma unroll 4
        for (int r = 0; r < 32; r++) {
            int i = rbase + r;
            bool hit = false;
            if (i < KK) {
                float4 bi = g_sb4[i];   // broadcast load
                float ai = (bi.z - bi.x + 1.f) * (bi.w - bi.y + 1.f);
                if (jv && j > i) {
                    float xx1 = fmaxf(bi.x, bj.x), yy1 = fmaxf(bi.y, bj.y);
                    float xx2 = fminf(bi.z, bj.z), yy2 = fminf(bi.w, bj.w);
                    float iw = fmaxf(xx2 - xx1 + 1.f, 0.f);
                    float ih = fmaxf(yy2 - yy1 + 1.f, 0.f);
                    float inter = iw * ih;
                    float iou = inter / (ai + aj - inter);
                    hit = (iou > 0.7f);
                }
            }
            unsigned m = __ballot_sync(0xffffffffu, hit);
            if (lane == r) myword = m;
        }
        int i = rbase + lane;
        if (i < KK) g_mask[i * NWRD + cw] = myword;
    }
}

// ---------------- tail: block 0 = NMS scan, block 1 = target+loss -----------
__global__ void k_tail(const float* __restrict__ gtb, float* out) {
    // shared for scan
    __shared__ unsigned s_remv[NWRD];
    __shared__ unsigned s_keep[NWRD];
    __shared__ unsigned s_diag[3][32];
    __shared__ unsigned s_next[3][32];
    __shared__ unsigned s_prio;
    __shared__ int pfx[NWRD + 1];
    // shared for tl
    __shared__ float cm[32 * 5];
    __shared__ float colmax[5];
    __shared__ int cnt0, cnt1;
    __shared__ double redd[32];

    int t = threadIdx.x;  // 1024
    int lane = t & 31, wrp = t >> 5;

    if (blockIdx.x == 0) {
        // ================= NMS scan =================
        if (t < NWRD) s_remv[t] = 0u;
        if (t == 0) s_prio = 0u;
        if (wrp == 1) {
            int i0 = lane;
            s_diag[0][lane] = g_mask[i0 * NWRD + 0];
            s_next[0][lane] = g_mask[i0 * NWRD + 1];
            int i1 = 32 + lane;
            s_diag[1][lane] = g_mask[i1 * NWRD + 1];
            s_next[1][lane] = g_mask[i1 * NWRD + 2];
        }
        __syncthreads();

        for (int s = 0; s < NWRD; s++) {
            int cur = s % 3;
            if (wrp == 1 && s + 2 < NWRD) {
                int i = (s + 2) * 32 + lane;
                unsigned dv = 0u, nv = 0u;
                if (i < KK) {
                    dv = g_mask[i * NWRD + (s + 2)];
                    if (s + 3 < NWRD) nv = g_mask[i * NWRD + (s + 3)];
                }
                s_diag[(s + 2) % 3][lane] = dv;
                s_next[(s + 2) % 3][lane] = nv;
            }
            if (wrp == 0) {
                unsigned nx = s_next[cur][lane];
                unsigned keep = 0u;
                if (lane == 0) {
                    unsigned d[32];
#pragma unroll
                    for (int b = 0; b < 32; b++) d[b] = s_diag[cur][b];
                    unsigned actb = ~(s_remv[s] | s_prio);
                    int lim = KK - s * 32; if (lim > 32) lim = 32;
#pragma unroll 8
                    for (int b = 0; b < 32; b++) {
                        if (b < lim && ((actb >> b) & 1u)) {
                            keep |= (1u << b);
                            actb &= ~d[b];
                        }
                    }
                    s_keep[s] = keep;
                }
                keep = __shfl_sync(0xffffffffu, keep, 0);
                unsigned v = ((keep >> lane) & 1u) ? nx : 0u;
#pragma unroll
                for (int o = 16; o > 0; o >>= 1)
                    v |= __shfl_xor_sync(0xffffffffu, v, o);
                if (lane == 0) s_prio = v;
            }
            if (wrp >= 2 && s >= 1) {
                unsigned kp = s_keep[s - 1];
                if (kp) {
                    int rbase = (s - 1) * 32;
                    // 30 warps -> each thread handles at most one word
                    for (int wd = s + 1 + (t - 64); wd < NWRD; wd += 960) {
                        unsigned acc = 0u;
                        unsigned k2 = kp;
                        while (k2) {
                            int b0 = __ffs(k2) - 1; k2 &= k2 - 1;
                            int b1 = -1, b2 = -1, b3 = -1;
                            if (k2) { b1 = __ffs(k2) - 1; k2 &= k2 - 1; }
                            if (k2) { b2 = __ffs(k2) - 1; k2 &= k2 - 1; }
                            if (k2) { b3 = __ffs(k2) - 1; k2 &= k2 - 1; }
                            unsigned m0 = g_mask[(rbase + b0) * NWRD + wd];
                            unsigned m1 = (b1 >= 0) ? g_mask[(rbase + b1) * NWRD + wd] : 0u;
                            unsigned m2 = (b2 >= 0) ? g_mask[(rbase + b2) * NWRD + wd] : 0u;
                            unsigned m3 = (b3 >= 0) ? g_mask[(rbase + b3) * NWRD + wd] : 0u;
                            acc |= (m0 | m1) | (m2 | m3);
                        }
                        s_remv[wd] |= acc;
                    }
                }
            }
            __syncthreads();
        }

        if (t == 0) {
            int s = 0;
            for (int w = 0; w < NWRD; w++) { pfx[w] = s; s += __popc(s_keep[w]); }
            pfx[NWRD] = s;
        }
        __syncthreads();
        if (t < NWRD) {
            unsigned kp = s_keep[t];
            int r = pfx[t];
            while (kp) {
                int b = __ffs(kp) - 1;
                kp &= kp - 1;
                int i = t * 32 + b;
                if (r < POST && g_ss[i] > -1e8f) {
                    float4 bb = g_sb4[i];
                    out[3 + r * 5 + 1] = bb.x;
                    out[3 + r * 5 + 2] = bb.y;
                    out[3 + r * 5 + 3] = bb.z;
                    out[3 + r * 5 + 4] = bb.w;
                }
                r++;
            }
        }
        return;
    }

    // ================= target + losses (block 1) =================
    if (t == 0) { cnt0 = 0; cnt1 = 0; }
    float gx1[5], gy1[5], gx2[5], gy2[5], ga[5];
#pragma unroll
    for (int g = 0; g < 5; g++) {
        gx1[g] = gtb[g * 5 + 0]; gy1[g] = gtb[g * 5 + 1];
        gx2[g] = gtb[g * 5 + 2]; gy2[g] = gtb[g * 5 + 3];
        ga[g] = (gx2[g] - gx1[g] + 1.f) * (gy2[g] - gy1[g] + 1.f);
    }
    float pc[5] = {-FLT_MAX, -FLT_MAX, -FLT_MAX, -FLT_MAX, -FLT_MAX};
    __syncthreads();
    for (int k = t; k < KK; k += 1024) {
        float ax1, ay1, ax2, ay2; bool ins;
        get_anchor(k, ax1, ay1, ax2, ay2, ins);
        float aa = (ax2 - ax1 + 1.f) * (ay2 - ay1 + 1.f);
        float best = -FLT_MAX; int bg = 0;
#pragma unroll
        for (int g = 0; g < 5; g++) {
            float xx1 = fmaxf(ax1, gx1[g]), yy1 = fmaxf(ay1, gy1[g]);
            float xx2 = fminf(ax2, gx2[g]), yy2 = fminf(ay2, gy2[g]);
            float iw = fmaxf(xx2 - xx1 + 1.f, 0.f);
            float ih = fmaxf(yy2 - yy1 + 1.f, 0.f);
            float inter = iw * ih;
            float ov = inter / (aa + ga[g] - inter);
            ov = ins ? ov : -1.f;
            g_ov[k * 5 + g] = ov;
            pc[g] = fmaxf(pc[g], ov);
            if (ov > best) { best = ov; bg = g; }
        }
        g_maxov[k] = best;
        g_arg[k] = bg;
    }
#pragma unroll
    for (int g = 0; g < 5; g++) {
        float v = pc[g];
#pragma unroll
        for (int o = 16; o > 0; o >>= 1) v = fmaxf(v, __shfl_down_sync(0xffffffffu, v, o));
        if ((t & 31) == 0) cm[(t >> 5) * 5 + g] = v;
    }
    __syncthreads();
    if (t < 5) {
        float v = -FLT_MAX;
        for (int wpi = 0; wpi < 32; wpi++) v = fmaxf(v, cm[wpi * 5 + t]);
        colmax[t] = v;
    }
    __syncthreads();
    for (int k = t; k < KK; k += 1024) {
        float ax1, ay1, ax2, ay2; bool ins;
        get_anchor(k, ax1, ay1, ax2, ay2, ins);
        float mo = g_maxov[k];
        int lab = -1;
        if (ins && mo < 0.3f) lab = 0;
        bool gb = false;
#pragma unroll
        for (int g = 0; g < 5; g++)
            if (g_ov[k * 5 + g] == colmax[g]) gb = true;
        if (gb && ins) lab = 1;
        if (ins && mo >= 0.7f) lab = 1;
        g_labels[k] = lab;
        if (lab >= 0) atomicAdd(&cnt0, 1);
        if (lab == 1) atomicAdd(&cnt1, 1);
    }
    __syncthreads();

    int nex = cnt0, nfg = cnt1;
    float num_ex = (float)(nex > 1 ? nex : 1);
    double scls = 0.0, sbox = 0.0, sact = 0.0;

    for (int i = t; i < KK; i += 1024) {
        int a = i / 300, pos = i - a * 300;
        int lab = g_labels[pos * 12 + a];
        if (lab != -1) {
            float x0 = g_y2[a * 300 + pos], x1 = g_y2[(12 + a) * 300 + pos];
            float m = fmaxf(x0, x1);
            float lse = m + logf(expf(x0 - m) + expf(x1 - m));
            float xl = lab ? x1 : x0;
            scls += (double)(lse - xl);
        }
    }

    for (int e = t; e < 14400; e += 1024) {
        int ch = e / 300, pos = e - ch * 300;
        int a = ch >> 2, c = ch & 3;
        int k = pos * 12 + a;
        int lab = g_labels[k];
        float ow = (lab >= 0) ? (1.f / num_ex) : 0.f;
        float iw = (lab == 1) ? 1.f : 0.f;
        float ax1, ay1, ax2, ay2; bool ins;
        get_anchor(k, ax1, ay1, ax2, ay2, ins);
        float tgt = 0.f;
        if (ins) {
            int g = g_arg[k];
            float gx1v = gtb[g * 5 + 0], gy1v = gtb[g * 5 + 1];
            float gx2v = gtb[g * 5 + 2], gy2v = gtb[g * 5 + 3];
            float ew = ax2 - ax1 + 1.f, eh = ay2 - ay1 + 1.f;
            float ecx = ax1 + 0.5f * ew, ecy = ay1 + 0.5f * eh;
            float gw = gx2v - gx1v + 1.f, gh = gy2v - gy1v + 1.f;
            float gcx = gx1v + 0.5f * gw, gcy = gy1v + 0.5f * gh;
            float tv;
            if (c == 0) tv = (gcx - ecx) / ew;
            else if (c == 1) tv = (gcy - ecy) / eh;
            else if (c == 2) tv = logf(gw / ew);
            else tv = logf(gh / eh);
            tgt = tv;
        }
        float pred = g_y2[(24 + ch) * 300 + pos];
        float d = iw * (pred - tgt);
        float ad = fabsf(d);
        float loss = (ad < (1.f / 9.f)) ? (0.5f * 9.f * d * d) : (ad - 0.5f / 9.f);
        sbox += (double)(ow * loss);
    }

    int gl = (int)gtb[4];
    for (int i = t; i < KK; i += 1024) {
        int a = i / 300, pos = i - a * 300;
        if (g_labels[pos * 12 + a] == 1) {
            float sa[22];
            float mx = -FLT_MAX;
#pragma unroll
            for (int n = 0; n < 22; n++) {
                int idx = i * 22 + n;
                int ch = idx / 300, pp = idx - ch * 300;
                float v = g_y2[(72 + ch) * 300 + pp];
                float s = 1.f / (1.f + expf(-v));
                sa[n] = s;
                mx = fmaxf(mx, s);
            }
            float se = 0.f;
#pragma unroll
            for (int n = 0; n < 22; n++) se += expf(sa[n] - mx);
            sact += (double)(mx + logf(se) - sa[gl]);
        }
    }

    double rs = blk_sumd(scls, redd, t);
    double rb = blk_sumd(sbox, redd, t);
    double ra = blk_sumd(sact, redd, t);
    if (t == 0) {
        out[0] = (float)((rs / (double)nex) / 8.0);
        out[1] = (float)(rb / 8.0);
        out[2] = (float)(ra / (double)nfg);
    }
}

// ---------------- launch ----------------
extern "C" void kernel_launch(void* const* d_in, const int* in_sizes, int n_in,
                              void* d_out, int out_size) {
    const float* x   = (const float*)d_in[0];
    const float* gtb = (const float*)d_in[1];
    const float* w1  = (const float*)d_in[3];
    const float* b1  = (const float*)d_in[4];
    const float* g1  = (const float*)d_in[5];
    const float* bb1 = (const float*)d_in[6];
    const float* w2  = (const float*)d_in[7];
    const float* b2  = (const float*)d_in[8];
    const float* g2  = (const float*)d_in[9];
    const float* bb2 = (const float*)d_in[10];
    float* out = (float*)d_out;

    k_conv1<<<256, 320>>>(x, w1, b1, g1, bb1);   // 1
    k_conv2<<<84, 640>>>(w2, b2, g2, bb2);       // 2
    k_sort<<<1, 1024>>>();                       // 3
    k_mask<<<148, 512>>>(out, out_size);         // 4 (profiled)
    k_tail<<<2, 1024>>>(gtb, out);               // 5 (scan || target+loss)
}

// round 17
// speedup vs baseline: 1.3304x; 1.0253x over previous
#include <cuda_runtime.h>
#include <math.h>
#include <float.h>

#define HH 15
#define WW 20
#define AA 12
#define KK 3600
#define NWRD 113      // ceil(3600/32)
#define POST 2000
#define NTILE 6441    // 113*114/2 upper-triangle 32x32 tiles
#define NWARPS_MASK 2368  // 148 blocks * 16 warps

// ---------------- scratch (no allocations allowed) ----------------
__device__ float    g_relu1[512*300];
__device__ float    g_y2[336*300];
__device__ float    g_boxes[KK*4];
__device__ float4   g_sb4[KK];
__device__ float    g_ss[KK];
__device__ float    g_areas[KK];
__device__ unsigned g_mask[KK*NWRD];
__device__ float    g_ov[KK*5];
__device__ float    g_maxov[KK];
__device__ int      g_arg[KK];
__device__ int      g_labels[KK];
__device__ int      g_counts[2];

// ---------------- packed f32x2 helpers (Blackwell) ----------------
__device__ __forceinline__ unsigned long long pk2(float lo, float hi) {
    unsigned long long r;
    asm("mov.b64 %0, {%1, %2};" : "=l"(r) : "f"(lo), "f"(hi));
    return r;
}
__device__ __forceinline__ void unpk2(unsigned long long v, float& lo, float& hi) {
    asm("mov.b64 {%0, %1}, %2;" : "=f"(lo), "=f"(hi) : "l"(v));
}
__device__ __forceinline__ void fma2(unsigned long long& d,
                                     unsigned long long a, unsigned long long b) {
    asm("fma.rn.f32x2 %0, %1, %2, %0;" : "+l"(d) : "l"(a), "l"(b));
}

// ---------------- helpers ----------------
__device__ __forceinline__ void get_anchor(int k, float& x1, float& y1,
                                           float& x2, float& y2, bool& ins) {
    int a = k % AA;  int pos = k / AA;
    int h = pos / WW, w = pos % WW;
    int r = a >> 2, s = a & 3;
    int wsi = (r == 0) ? 23 : ((r == 1) ? 16 : 11);
    int hsi = (r == 0) ? 12 : ((r == 1) ? 16 : 22);
    int scl = 4 << s;
    float wwf = (float)(wsi * scl), hhf = (float)(hsi * scl);
    float sx = (float)(w * 16), sy = (float)(h * 16);
    x1 = sx + 7.5f - 0.5f * (wwf - 1.f);
    y1 = sy + 7.5f - 0.5f * (hhf - 1.f);
    x2 = sx + 7.5f + 0.5f * (wwf - 1.f);
    y2 = sy + 7.5f + 0.5f * (hhf - 1.f);
    ins = (x1 >= 0.f) && (y1 >= 0.f) && (x2 < 320.f) && (y2 < 240.f);
}

template <int NWARP>
__device__ __forceinline__ float blk_sum(float v, float* red, int tid) {
#pragma unroll
    for (int o = 16; o > 0; o >>= 1) v += __shfl_down_sync(0xffffffffu, v, o);
    if ((tid & 31) == 0) red[tid >> 5] = v;
    __syncthreads();
    float s;
    if (tid == 0) { s = 0.f; for (int i = 0; i < NWARP; i++) s += red[i]; red[31] = s; }
    __syncthreads();
    s = red[31];
    __syncthreads();
    return s;
}

__device__ __forceinline__ double blk_sumd(double v, double* red, int tid) {
#pragma unroll
    for (int o = 16; o > 0; o >>= 1) v += __shfl_down_sync(0xffffffffu, v, o);
    if ((tid & 31) == 0) red[tid >> 5] = v;
    __syncthreads();
    double s;
    if (tid == 0) { s = 0.0; for (int i = 0; i < 32; i++) s += red[i]; red[0] = s; }
    __syncthreads();
    s = red[0];
    __syncthreads();
    return s;
}

// ---------------- conv1 3x3 (512->512) + BN(train) + ReLU ----------------
// grid 256, block 320. Thread: 4 adjacent positions; 4-way ic split.
__global__ void k_conv1(const float* __restrict__ x, const float* __restrict__ wgt,
                        const float* __restrict__ bias, const float* __restrict__ gg,
                        const float* __restrict__ bb) {
    __shared__ float xs[16 * 374];                // 16 ic x (17*22) padded
    __shared__ __align__(16) float ws[16 * 20];   // [icl][tap*2+ocl], pad 18->20
    __shared__ unsigned short sdst[4800];
    __shared__ float part[1800];                  // 3 quarters x 75 x 8
    __shared__ float red[32];
    int tid = threadIdx.x;     // 320
    int oc0 = blockIdx.x * 2;
    int q = tid / 80;
    int lt = tid - q * 80;
    bool act = lt < 75;
    int h = lt / 5;
    int cg = (lt % 5) * 4;
    int icl0 = q * 4;
    unsigned long long qa[4] = {0, 0, 0, 0};
    unsigned long long qb[4] = {0, 0, 0, 0};

    for (int i = tid; i < 16 * 374; i += 320) xs[i] = 0.f;
    for (int i = tid; i < 4800; i += 320) {
        int icl = i / 300, p = i - icl * 300;
        sdst[i] = (unsigned short)(icl * 374 + (p / 20 + 1) * 22 + (p % 20 + 1));
    }
    __syncthreads();

    for (int cb = 0; cb < 32; cb++) {
        int icb = cb * 16;
        const float* xsrc = x + icb * 300;
#pragma unroll
        for (int i = tid; i < 4800; i += 320)
            xs[sdst[i]] = xsrc[i];
        if (tid < 288) {
            int icl = tid / 18, r = tid - icl * 18;
            int tap = r >> 1, ocl = r & 1;
            ws[icl * 20 + r] = wgt[(oc0 + ocl) * 4608 + (icb + icl) * 9 + tap];
        }
        __syncthreads();
        if (act) {
#pragma unroll
            for (int ii = 0; ii < 4; ii++) {
                int icl = icl0 + ii;
                const float* xp = &xs[icl * 374 + h * 22 + cg];
                float xv[3][6];
#pragma unroll
                for (int dh = 0; dh < 3; dh++) {
                    unsigned long long p01 =
                        *(const unsigned long long*)(xp + dh * 22);
                    unsigned long long p23 =
                        *(const unsigned long long*)(xp + dh * 22 + 2);
                    unsigned long long p45 =
                        *(const unsigned long long*)(xp + dh * 22 + 4);
                    unpk2(p01, xv[dh][0], xv[dh][1]);
                    unpk2(p23, xv[dh][2], xv[dh][3]);
                    unpk2(p45, xv[dh][4], xv[dh][5]);
                }
                const float* wb = &ws[icl * 20];
                unsigned long long wt[9];
                {
                    ulonglong2 wA = *(const ulonglong2*)(wb);
                    ulonglong2 wB = *(const ulonglong2*)(wb + 4);
                    ulonglong2 wC = *(const ulonglong2*)(wb + 8);
                    ulonglong2 wD = *(const ulonglong2*)(wb + 12);
                    wt[0] = wA.x; wt[1] = wA.y; wt[2] = wB.x; wt[3] = wB.y;
                    wt[4] = wC.x; wt[5] = wC.y; wt[6] = wD.x; wt[7] = wD.y;
                    wt[8] = *(const unsigned long long*)(wb + 16);
                }
#pragma unroll
                for (int dh = 0; dh < 3; dh++)
#pragma unroll
                    for (int dw = 0; dw < 3; dw++) {
                        int tap = dh * 3 + dw;
                        unsigned long long w01 = wt[tap];
                        if (tap & 1) {
#pragma unroll
                            for (int p = 0; p < 4; p++)
                                fma2(qb[p], w01, pk2(xv[dh][dw + p], xv[dh][dw + p]));
                        } else {
#pragma unroll
                            for (int p = 0; p < 4; p++)
                                fma2(qa[p], w01, pk2(xv[dh][dw + p], xv[dh][dw + p]));
                        }
                    }
            }
        }
        __syncthreads();
    }

    float v0[4], v1[4];
#pragma unroll
    for (int p = 0; p < 4; p++) {
        float t0, t1, t2, t3;
        unpk2(qa[p], t0, t1);
        unpk2(qb[p], t2, t3);
        v0[p] = t0 + t2;
        v1[p] = t1 + t3;
    }
    if (act && q > 0) {
        int b = (q - 1) * 600 + lt * 8;
#pragma unroll
        for (int p = 0; p < 4; p++) {
            part[b + p] = v0[p];
            part[b + 4 + p] = v1[p];
        }
    }
    __syncthreads();
    bool actF = act && (q == 0);
    if (actF) {
#pragma unroll
        for (int g = 0; g < 3; g++) {
            int b = g * 600 + lt * 8;
#pragma unroll
            for (int p = 0; p < 4; p++) {
                v0[p] += part[b + p];
                v1[p] += part[b + 4 + p];
            }
        }
#pragma unroll
        for (int p = 0; p < 4; p++) {
            v0[p] += bias[oc0 + 0];
            v1[p] += bias[oc0 + 1];
        }
    }
    int p0 = actF ? (h * 20 + cg) : 0;
#define BN_OC(V, OCL)                                                                  \
    {                                                                                  \
        float m = blk_sum<10>(actF ? (V[0] + V[1] + V[2] + V[3]) : 0.f, red, tid)      \
                  / 300.f;                                                             \
        float d0 = V[0] - m, d1 = V[1] - m, d2 = V[2] - m, d3 = V[3] - m;              \
        float vv = blk_sum<10>(                                                        \
                       actF ? (d0 * d0 + d1 * d1 + d2 * d2 + d3 * d3) : 0.f, red, tid) \
                   / 300.f;                                                            \
        if (actF) {                                                                    \
            float rs = rsqrtf(vv + 1e-5f) * gg[oc0 + OCL];                             \
            float bbv = bb[oc0 + OCL];                                                 \
            g_relu1[(oc0 + OCL) * 300 + p0 + 0] = fmaxf(d0 * rs + bbv, 0.f);           \
            g_relu1[(oc0 + OCL) * 300 + p0 + 1] = fmaxf(d1 * rs + bbv, 0.f);           \
            g_relu1[(oc0 + OCL) * 300 + p0 + 2] = fmaxf(d2 * rs + bbv, 0.f);           \
            g_relu1[(oc0 + OCL) * 300 + p0 + 3] = fmaxf(d3 * rs + bbv, 0.f);           \
        }                                                                              \
    }
    BN_OC(v0, 0)
    BN_OC(v1, 1)
#undef BN_OC
}

// ---------------- conv2 1x1 (512->336) + BN(train) ----------------
// grid 168, block 640. 2 oc per block; 2-way ic split (halves of 256 ic).
__global__ void k_conv2(const float* __restrict__ w2, const float* __restrict__ b2,
                        const float* __restrict__ g2, const float* __restrict__ bb2) {
    __shared__ __align__(16) float2 wst[512];   // [ic] -> (oc0, oc1)
    __shared__ float part[300 * 2];
    __shared__ float red[32];
    int tid = threadIdx.x;     // 640
    int oc0 = blockIdx.x * 2;
    int half = tid / 320;
    int lt = tid - half * 320;
    for (int i = tid; i < 1024; i += 640) {
        int ic = i >> 1, ocl = i & 1;
        ((float*)wst)[i] = w2[(oc0 + ocl) * 512 + ic];
    }
    __syncthreads();
    bool act = lt < 300;
    float a0 = 0, a1 = 0;
    if (act) {
        int ic0 = half * 256;
#pragma unroll 16
        for (int ii = 0; ii < 256; ii++) {
            int ic = ic0 + ii;
            float rv = g_relu1[ic * 300 + lt];
            float2 wv = wst[ic];
            a0 += wv.x * rv;
            a1 += wv.y * rv;
        }
    }
    if (act && half == 1) {
        part[lt * 2 + 0] = a0;
        part[lt * 2 + 1] = a1;
    }
    __syncthreads();
    bool actF = act && (half == 0);
    if (actF) {
        a0 += part[lt * 2 + 0];
        a1 += part[lt * 2 + 1];
        a0 += b2[oc0 + 0];
        a1 += b2[oc0 + 1];
    }
#define BN2_OC(A0, OCL)                                                         \
    {                                                                           \
        float m = blk_sum<20>(actF ? A0 : 0.f, red, tid) / 300.f;               \
        float d = A0 - m;                                                       \
        float vv = blk_sum<20>(actF ? d * d : 0.f, red, tid) / 300.f;           \
        if (actF) {                                                             \
            g_y2[(oc0 + OCL) * 300 + lt] =                                      \
                d * rsqrtf(vv + 1e-5f) * g2[oc0 + OCL] + bb2[oc0 + OCL];        \
        }                                                                       \
    }
    BN2_OC(a0, 0)
    BN2_OC(a1, 1)
#undef BN2_OC
}

// ---------------- fused props + u64 bitonic sort ----------------
__device__ __forceinline__ void cex64(unsigned long long& a, unsigned long long& b,
                                      bool asc) {
    bool sw = asc ? (a > b) : (a < b);
    if (sw) { unsigned long long t = a; a = b; b = t; }
}

__global__ void k_sort() {
    __shared__ unsigned long long sk[4096];
    int tid = threadIdx.x;  // 1024

    for (int k = tid; k < 4096; k += 1024) {
        float sc = -FLT_MAX;
        if (k < KK) {
            int a = k % AA, pos = k / AA;
            float ax1, ay1, ax2, ay2; bool ins;
            get_anchor(k, ax1, ay1, ax2, ay2, ins);
            float wA = ax2 - ax1 + 1.f, hA = ay2 - ay1 + 1.f;
            float cx = ax1 + 0.5f * wA, cy = ay1 + 0.5f * hA;
            float d0 = g_y2[(24 + 4 * a + 0) * 300 + pos];
            float d1 = g_y2[(24 + 4 * a + 1) * 300 + pos];
            float d2 = g_y2[(24 + 4 * a + 2) * 300 + pos];
            float d3 = g_y2[(24 + 4 * a + 3) * 300 + pos];
            float pcx = d0 * wA + cx, pcy = d1 * hA + cy;
            float pw = expf(d2) * wA, ph = expf(d3) * hA;
            float x1 = pcx - 0.5f * pw, y1 = pcy - 0.5f * ph;
            float x2 = pcx + 0.5f * pw, y2 = pcy + 0.5f * ph;
            x1 = fminf(fmaxf(x1, 0.f), 319.f);
            y1 = fminf(fmaxf(y1, 0.f), 239.f);
            x2 = fminf(fmaxf(x2, 0.f), 319.f);
            y2 = fminf(fmaxf(y2, 0.f), 239.f);
            float wsz = x2 - x1 + 1.f, hsz = y2 - y1 + 1.f;
            float c0 = g_y2[a * 300 + pos], c1 = g_y2[(AA + a) * 300 + pos];
            float mm = fmaxf(c0, c1);
            float e0 = expf(c0 - mm), e1 = expf(c1 - mm);
            sc = e1 / (e0 + e1);
            if (!((wsz >= 8.f) && (hsz >= 8.f))) sc = -1e9f;
            g_boxes[k * 4 + 0] = x1;
            g_boxes[k * 4 + 1] = y1;
            g_boxes[k * 4 + 2] = x2;
            g_boxes[k * 4 + 3] = y2;
        }
        unsigned u = __float_as_uint(sc);
        unsigned ou = (u & 0x80000000u) ? ~u : (u | 0x80000000u);
        sk[k] = ((unsigned long long)(~ou) << 32) | (unsigned)k;
    }
    __syncthreads();

    {
        int b4 = tid * 4;
        unsigned long long k0 = sk[b4], k1 = sk[b4 + 1],
                           k2 = sk[b4 + 2], k3 = sk[b4 + 3];
        cex64(k0, k1, true);
        cex64(k2, k3, false);
        bool d4 = ((b4 & 4) == 0);
        cex64(k0, k2, d4); cex64(k1, k3, d4);
        cex64(k0, k1, d4); cex64(k2, k3, d4);
        sk[b4] = k0; sk[b4 + 1] = k1; sk[b4 + 2] = k2; sk[b4 + 3] = k3;
    }
    __syncthreads();

    for (int size = 8; size <= 4096; size <<= 1) {
        for (int stride = size >> 1; stride >= 4; stride >>= 1) {
            for (int i = tid; i < 4096; i += 1024) {
                int j = i ^ stride;
                if (j > i) {
                    bool asc = ((i & size) == 0);
                    unsigned long long ki = sk[i], kj = sk[j];
                    bool sw = asc ? (ki > kj) : (ki < kj);
                    if (sw) { sk[i] = kj; sk[j] = ki; }
                }
            }
            __syncthreads();
        }
        {
            int b4 = tid * 4;
            unsigned long long k0 = sk[b4], k1 = sk[b4 + 1],
                               k2 = sk[b4 + 2], k3 = sk[b4 + 3];
            bool dd = ((b4 & size) == 0);
            cex64(k0, k2, dd); cex64(k1, k3, dd);
            cex64(k0, k1, dd); cex64(k2, k3, dd);
            sk[b4] = k0; sk[b4 + 1] = k1; sk[b4 + 2] = k2; sk[b4 + 3] = k3;
        }
        __syncthreads();
    }

    for (int i = tid; i < KK; i += 1024) {
        unsigned long long kk = sk[i];
        int v = (int)(kk & 0xFFFFFFFFu);
        unsigned ou = ~((unsigned)(kk >> 32));
        unsigned u = (ou & 0x80000000u) ? (ou & 0x7FFFFFFFu) : ~ou;
        g_ss[i] = __uint_as_float(u);
        float x1 = g_boxes[v * 4 + 0], y1 = g_boxes[v * 4 + 1];
        float x2 = g_boxes[v * 4 + 2], y2 = g_boxes[v * 4 + 3];
        g_sb4[i] = make_float4(x1, y1, x2, y2);
        g_areas[i] = (x2 - x1 + 1.f) * (y2 - y1 + 1.f);
    }
}

// ---------------- NMS suppression bitmask (warp-per-32x32-tile) --------------
// grid 148 (1 block/SM), block 512.
__global__ void k_mask(float* out, int out_size) {
    for (int i = blockIdx.x * 512 + threadIdx.x; i < out_size; i += 148 * 512)
        out[i] = 0.f;
    int lane = threadIdx.x & 31;
    int gw = blockIdx.x * 16 + (threadIdx.x >> 5);
    for (int tile = gw; tile < NTILE; tile += NWARPS_MASK) {
        int rw = (int)(113.5f - sqrtf(113.5f * 113.5f - 2.f * (float)tile));
        if (rw < 0) rw = 0;
        while ((rw + 1) * 113 - ((rw + 1) * rw) / 2 <= tile) rw++;
        while (rw * 113 - (rw * (rw - 1)) / 2 > tile) rw--;
        int cw = rw + (tile - (rw * 113 - (rw * (rw - 1)) / 2));
        int j = cw * 32 + lane;
        float4 bj = make_float4(0, 0, 0, 0);
        float aj = 1.f;
        bool jv = (j < KK);
        if (jv) {
            bj = g_sb4[j];
            aj = (bj.z - bj.x + 1.f) * (bj.w - bj.y + 1.f);
        }
        int rbase = rw * 32;
        unsigned myword = 0u;
#pragma unroll 4
        for (int r = 0; r < 32; r++) {
            int i = rbase + r;
            bool hit = false;
            if (i < KK) {
                float4 bi = g_sb4[i];   // broadcast load
                float ai = (bi.z - bi.x + 1.f) * (bi.w - bi.y + 1.f);
                if (jv && j > i) {
                    float xx1 = fmaxf(bi.x, bj.x), yy1 = fmaxf(bi.y, bj.y);
                    float xx2 = fminf(bi.z, bj.z), yy2 = fminf(bi.w, bj.w);
                    float iw = fmaxf(xx2 - xx1 + 1.f, 0.f);
                    float ih = fmaxf(yy2 - yy1 + 1.f, 0.f);
                    float inter = iw * ih;
                    float iou = inter / (ai + aj - inter);
                    hit = (iou > 0.7f);
                }
            }
            unsigned m = __ballot_sync(0xffffffffu, hit);
            if (lane == r) myword = m;
        }
        int i = rbase + lane;
        if (i < KK) g_mask[i * NWRD + cw] = myword;
    }
}

// ---------------- tail: block 0 = NMS scan, block 1 = target+loss -----------
__global__ void k_tail(const float* __restrict__ gtb, float* out) {
    // shared for scan
    __shared__ unsigned s_remv[NWRD];
    __shared__ unsigned s_keep[NWRD];
    __shared__ unsigned s_diag[3][32];
    __shared__ unsigned s_next[3][32];
    __shared__ unsigned s_prio;
    __shared__ int pfx[NWRD + 1];
    // shared for tl
    __shared__ float cm[32 * 5];
    __shared__ float colmax[5];
    __shared__ int cnt0, cnt1;
    __shared__ double redd[32];

    int t = threadIdx.x;  // 1024
    int lane = t & 31, wrp = t >> 5;

    if (blockIdx.x == 0) {
        // ================= NMS scan =================
        if (t < NWRD) s_remv[t] = 0u;
        if (t == 0) s_prio = 0u;
        if (wrp == 1) {
            int i0 = lane;
            s_diag[0][lane] = g_mask[i0 * NWRD + 0];
            s_next[0][lane] = g_mask[i0 * NWRD + 1];
            int i1 = 32 + lane;
            s_diag[1][lane] = g_mask[i1 * NWRD + 1];
            s_next[1][lane] = g_mask[i1 * NWRD + 2];
        }
        __syncthreads();

        for (int s = 0; s < NWRD; s++) {
            int cur = s % 3;
            if (wrp == 1 && s + 2 < NWRD) {
                int i = (s + 2) * 32 + lane;
                unsigned dv = 0u, nv = 0u;
                if (i < KK) {
                    dv = g_mask[i * NWRD + (s + 2)];
                    if (s + 3 < NWRD) nv = g_mask[i * NWRD + (s + 3)];
                }
                s_diag[(s + 2) % 3][lane] = dv;
                s_next[(s + 2) % 3][lane] = nv;
            }
            if (wrp == 0) {
                unsigned nx = s_next[cur][lane];
                unsigned keep = 0u;
                if (lane == 0) {
                    int lim = KK - s * 32;
                    unsigned valid = (lim >= 32) ? 0xffffffffu
                                                 : ((1u << lim) - 1u);
                    unsigned actb = ~(s_remv[s] | s_prio) & valid;
                    // fully unrolled: s_diag reads at constant indices stay
                    // in registers (no local-memory spill)
#pragma unroll
                    for (int b = 0; b < 32; b++) {
                        unsigned bit = 1u << b;
                        if (actb & bit) {
                            keep |= bit;
                            actb &= ~s_diag[cur][b];
                        }
                    }
                    s_keep[s] = keep;
                }
                keep = __shfl_sync(0xffffffffu, keep, 0);
                unsigned v = ((keep >> lane) & 1u) ? nx : 0u;
#pragma unroll
                for (int o = 16; o > 0; o >>= 1)
                    v |= __shfl_xor_sync(0xffffffffu, v, o);
                if (lane == 0) s_prio = v;
            }
            if (wrp >= 2 && s >= 1) {
                unsigned kp = s_keep[s - 1];
                if (kp) {
                    int rbase = (s - 1) * 32;
                    for (int wd = s + 1 + (t - 64); wd < NWRD; wd += 960) {
                        unsigned acc = 0u;
                        unsigned k2 = kp;
                        while (k2) {
                            int b0 = __ffs(k2) - 1; k2 &= k2 - 1;
                            int b1 = -1, b2 = -1, b3 = -1;
                            if (k2) { b1 = __ffs(k2) - 1; k2 &= k2 - 1; }
                            if (k2) { b2 = __ffs(k2) - 1; k2 &= k2 - 1; }
                            if (k2) { b3 = __ffs(k2) - 1; k2 &= k2 - 1; }
                            unsigned m0 = g_mask[(rbase + b0) * NWRD + wd];
                            unsigned m1 = (b1 >= 0) ? g_mask[(rbase + b1) * NWRD + wd] : 0u;
                            unsigned m2 = (b2 >= 0) ? g_mask[(rbase + b2) * NWRD + wd] : 0u;
                            unsigned m3 = (b3 >= 0) ? g_mask[(rbase + b3) * NWRD + wd] : 0u;
                            acc |= (m0 | m1) | (m2 | m3);
                        }
                        s_remv[wd] |= acc;
                    }
                }
            }
            __syncthreads();
        }

        if (t == 0) {
            int s = 0;
            for (int w = 0; w < NWRD; w++) { pfx[w] = s; s += __popc(s_keep[w]); }
            pfx[NWRD] = s;
        }
        __syncthreads();
        if (t < NWRD) {
            unsigned kp = s_keep[t];
            int r = pfx[t];
            while (kp) {
                int b = __ffs(kp) - 1;
                kp &= kp - 1;
                int i = t * 32 + b;
                if (r < POST && g_ss[i] > -1e8f) {
                    float4 bb = g_sb4[i];
                    out[3 + r * 5 + 1] = bb.x;
                    out[3 + r * 5 + 2] = bb.y;
                    out[3 + r * 5 + 3] = bb.z;
                    out[3 + r * 5 + 4] = bb.w;
                }
                r++;
            }
        }
        return;
    }

    // ================= target + losses (block 1) =================
    if (t == 0) { cnt0 = 0; cnt1 = 0; }
    float gx1[5], gy1[5], gx2[5], gy2[5], ga[5];
#pragma unroll
    for (int g = 0; g < 5; g++) {
        gx1[g] = gtb[g * 5 + 0]; gy1[g] = gtb[g * 5 + 1];
        gx2[g] = gtb[g * 5 + 2]; gy2[g] = gtb[g * 5 + 3];
        ga[g] = (gx2[g] - gx1[g] + 1.f) * (gy2[g] - gy1[g] + 1.f);
    }
    float pc[5] = {-FLT_MAX, -FLT_MAX, -FLT_MAX, -FLT_MAX, -FLT_MAX};
    __syncthreads();
    for (int k = t; k < KK; k += 1024) {
        float ax1, ay1, ax2, ay2; bool ins;
        get_anchor(k, ax1, ay1, ax2, ay2, ins);
        float aa = (ax2 - ax1 + 1.f) * (ay2 - ay1 + 1.f);
        float best = -FLT_MAX; int bg = 0;
#pragma unroll
        for (int g = 0; g < 5; g++) {
            float xx1 = fmaxf(ax1, gx1[g]), yy1 = fmaxf(ay1, gy1[g]);
            float xx2 = fminf(ax2, gx2[g]), yy2 = fminf(ay2, gy2[g]);
            float iw = fmaxf(xx2 - xx1 + 1.f, 0.f);
            float ih = fmaxf(yy2 - yy1 + 1.f, 0.f);
            float inter = iw * ih;
            float ov = inter / (aa + ga[g] - inter);
            ov = ins ? ov : -1.f;
            g_ov[k * 5 + g] = ov;
            pc[g] = fmaxf(pc[g], ov);
            if (ov > best) { best = ov; bg = g; }
        }
        g_maxov[k] = best;
        g_arg[k] = bg;
    }
#pragma unroll
    for (int g = 0; g < 5; g++) {
        float v = pc[g];
#pragma unroll
        for (int o = 16; o > 0; o >>= 1) v = fmaxf(v, __shfl_down_sync(0xffffffffu, v, o));
        if ((t & 31) == 0) cm[(t >> 5) * 5 + g] = v;
    }
    __syncthreads();
    if (t < 5) {
        float v = -FLT_MAX;
        for (int wpi = 0; wpi < 32; wpi++) v = fmaxf(v, cm[wpi * 5 + t]);
        colmax[t] = v;
    }
    __syncthreads();
    for (int k = t; k < KK; k += 1024) {
        float ax1, ay1, ax2, ay2; bool ins;
        get_anchor(k, ax1, ay1, ax2, ay2, ins);
        float mo = g_maxov[k];
        int lab = -1;
        if (ins && mo < 0.3f) lab = 0;
        bool gb = false;
#pragma unroll
        for (int g = 0; g < 5; g++)
            if (g_ov[k * 5 + g] == colmax[g]) gb = true;
        if (gb && ins) lab = 1;
        if (ins && mo >= 0.7f) lab = 1;
        g_labels[k] = lab;
        if (lab >= 0) atomicAdd(&cnt0, 1);
        if (lab == 1) atomicAdd(&cnt1, 1);
    }
    __syncthreads();

    int nex = cnt0, nfg = cnt1;
    float num_ex = (float)(nex > 1 ? nex : 1);
    double scls = 0.0, sbox = 0.0, sact = 0.0;

    for (int i = t; i < KK; i += 1024) {
        int a = i / 300, pos = i - a * 300;
        int lab = g_labels[pos * 12 + a];
        if (lab != -1) {
            float x0 = g_y2[a * 300 + pos], x1 = g_y2[(12 + a) * 300 + pos];
            float m = fmaxf(x0, x1);
            float lse = m + logf(expf(x0 - m) + expf(x1 - m));
            float xl = lab ? x1 : x0;
            scls += (double)(lse - xl);
        }
    }

    for (int e = t; e < 14400; e += 1024) {
        int ch = e / 300, pos = e - ch * 300;
        int a = ch >> 2, c = ch & 3;
        int k = pos * 12 + a;
        int lab = g_labels[k];
        float ow = (lab >= 0) ? (1.f / num_ex) : 0.f;
        float iw = (lab == 1) ? 1.f : 0.f;
        float ax1, ay1, ax2, ay2; bool ins;
        get_anchor(k, ax1, ay1, ax2, ay2, ins);
        float tgt = 0.f;
        if (ins) {
            int g = g_arg[k];
            float gx1v = gtb[g * 5 + 0], gy1v = gtb[g * 5 + 1];
            float gx2v = gtb[g * 5 + 2], gy2v = gtb[g * 5 + 3];
            float ew = ax2 - ax1 + 1.f, eh = ay2 - ay1 + 1.f;
            float ecx = ax1 + 0.5f * ew, ecy = ay1 + 0.5f * eh;
            float gw = gx2v - gx1v + 1.f, gh = gy2v - gy1v + 1.f;
            float gcx = gx1v + 0.5f * gw, gcy = gy1v + 0.5f * gh;
            float tv;
            if (c == 0) tv = (gcx - ecx) / ew;
            else if (c == 1) tv = (gcy - ecy) / eh;
            else if (c == 2) tv = logf(gw / ew);
            else tv = logf(gh / eh);
            tgt = tv;
        }
        float pred = g_y2[(24 + ch) * 300 + pos];
        float d = iw * (pred - tgt);
        float ad = fabsf(d);
        float loss = (ad < (1.f / 9.f)) ? (0.5f * 9.f * d * d) : (ad - 0.5f / 9.f);
        sbox += (double)(ow * loss);
    }

    int gl = (int)gtb[4];
    for (int i = t; i < KK; i += 1024) {
        int a = i / 300, pos = i - a * 300;
        if (g_labels[pos * 12 + a] == 1) {
            float sa[22];
            float mx = -FLT_MAX;
#pragma unroll
            for (int n = 0; n < 22; n++) {
                int idx = i * 22 + n;
                int ch = idx / 300, pp = idx - ch * 300;
                float v = g_y2[(72 + ch) * 300 + pp];
                float s = 1.f / (1.f + expf(-v));
                sa[n] = s;
                mx = fmaxf(mx, s);
            }
            float se = 0.f;
#pragma unroll
            for (int n = 0; n < 22; n++) se += expf(sa[n] - mx);
            sact += (double)(mx + logf(se) - sa[gl]);
        }
    }

    double rs = blk_sumd(scls, redd, t);
    double rb = blk_sumd(sbox, redd, t);
    double ra = blk_sumd(sact, redd, t);
    if (t == 0) {
        out[0] = (float)((rs / (double)nex) / 8.0);
        out[1] = (float)(rb / 8.0);
        out[2] = (float)(ra / (double)nfg);
    }
}

// ---------------- launch ----------------
extern "C" void kernel_launch(void* const* d_in, const int* in_sizes, int n_in,
                              void* d_out, int out_size) {
    const float* x   = (const float*)d_in[0];
    const float* gtb = (const float*)d_in[1];
    const float* w1  = (const float*)d_in[3];
    const float* b1  = (const float*)d_in[4];
    const float* g1  = (const float*)d_in[5];
    const float* bb1 = (const float*)d_in[6];
    const float* w2  = (const float*)d_in[7];
    const float* b2  = (const float*)d_in[8];
    const float* g2  = (const float*)d_in[9];
    const float* bb2 = (const float*)d_in[10];
    float* out = (float*)d_out;

    k_conv1<<<256, 320>>>(x, w1, b1, g1, bb1);   // 1
    k_conv2<<<168, 640>>>(w2, b2, g2, bb2);      // 2
    k_sort<<<1, 1024>>>();                       // 3
    k_mask<<<148, 512>>>(out, out_size);         // 4 (profiled)
    k_tail<<<2, 1024>>>(gtb, out);               // 5 (scan || target+loss)
}